// round 8
// baseline (speedup 1.0000x reference)
#include <cuda_runtime.h>
#include <cuda_bf16.h>
#include <cstdint>

#define BB 16
#define C1 256
#define CMID 128
#define CS 64
#define HH 80
#define WW 80
#define HW 6400

// ---------------- scratch (device globals; no allocations) ----------------
__device__ float g_h[(size_t)BB*CMID*HW];     // reduce output (hs ch 0..63, hb 64..127)
__device__ float g_omp[(size_t)8*BB*3*HW];    // offset conv partials (8 channel groups)
__device__ float4 g_spw[(size_t)BB*HW];       // bilinear weights (mask folded)
__device__ int4   g_spi[(size_t)BB*HW];       // gather indices (clamped)
__device__ float g_t1[(size_t)BB*CS*HW];      // dcn depthwise out
__device__ float g_dcn[(size_t)BB*CS*HW];     // dcn branch
__device__ float g_star[(size_t)BB*CS*HW];    // star0 = bn_star(dcn*ctx)
__device__ float g_chmean[BB*CS];             // raw channel sums (atomic)
__device__ float g_ych[BB*CS];
__device__ float g_spmean[(size_t)BB*HW];
__device__ float g_spmax[(size_t)BB*HW];
__device__ float g_satt[(size_t)BB*HW];
// pre-split bf16 hi/lo weights (k-pair packed)
__device__ uint32_t g_wred_h[128*128], g_wred_l[128*128];
__device__ uint32_t g_wexp_h[256*64],  g_wexp_l[256*64];
__device__ uint32_t g_wpw_h[64*32],    g_wpw_l[64*32];

__device__ __forceinline__ float siluf(float v) { return v / (1.f + __expf(-v)); }
__device__ __forceinline__ float sigf(float v)  { return 1.f / (1.f + __expf(-v)); }

// ---------------- mma.sync helpers ----------------
__device__ __forceinline__ void mma16816(float* c, const uint32_t* a, const uint32_t* b) {
    asm volatile(
        "mma.sync.aligned.m16n8k16.row.col.f32.bf16.bf16.f32 "
        "{%0,%1,%2,%3}, {%4,%5,%6,%7}, {%8,%9}, {%0,%1,%2,%3};"
        : "+f"(c[0]), "+f"(c[1]), "+f"(c[2]), "+f"(c[3])
        : "r"(a[0]), "r"(a[1]), "r"(a[2]), "r"(a[3]), "r"(b[0]), "r"(b[1]));
}

__device__ __forceinline__ void split2(float v0, float v1, uint32_t& hi, uint32_t& lo) {
    __nv_bfloat16 h0 = __float2bfloat16(v0);
    __nv_bfloat16 h1 = __float2bfloat16(v1);
    __nv_bfloat16 l0 = __float2bfloat16(v0 - __bfloat162float(h0));
    __nv_bfloat16 l1 = __float2bfloat16(v1 - __bfloat162float(h1));
    __nv_bfloat162 th(h0, h1), tl(l0, l1);
    hi = *(uint32_t*)&th;
    lo = *(uint32_t*)&tl;
}

#define TSTRIDE 144
#define TILE_BYTES (128 * TSTRIDE)           // 18432
#define OFF_A_HI 0
#define OFF_A_LO TILE_BYTES
#define OFF_B_HI (2 * TILE_BYTES)
#define OFF_B_LO (3 * TILE_BYTES)
#define GEMM_SMEM (4 * TILE_BYTES)           // 73728

#define PW_A_HI 0
#define PW_A_LO (64 * TSTRIDE)
#define PW_B_HI (2 * 64 * TSTRIDE)
#define PW_B_LO (PW_B_HI + 128 * TSTRIDE)
#define PW_SMEM (PW_B_LO + 128 * TSTRIDE)    // 55296

// ---------------- K0: zero channel-sum accumulator ----------------
__global__ void k_zero() {
    g_chmean[blockIdx.x * 256 + threadIdx.x] = 0.f;
}

// ---------------- K0b: pre-split GEMM weights to bf16 hi/lo ----------------
__global__ void k_prepw(const float* __restrict__ wred, const float* __restrict__ wexp,
                        const float* __restrict__ wpw) {
    int idx = blockIdx.x * 256 + threadIdx.x;   // 0..34815
    if (idx < 16384) {
        int oc = idx >> 7, j = idx & 127;
        split2(wred[oc * 256 + 2 * j], wred[oc * 256 + 2 * j + 1],
               g_wred_h[idx], g_wred_l[idx]);
    } else if (idx < 32768) {
        int q = idx - 16384;
        int oc = q >> 6, j = q & 63;
        split2(wexp[oc * 128 + 2 * j], wexp[oc * 128 + 2 * j + 1],
               g_wexp_h[q], g_wexp_l[q]);
    } else {
        int q = idx - 32768;
        int oc = q >> 5, j = q & 31;
        split2(wpw[oc * 64 + 2 * j], wpw[oc * 64 + 2 * j + 1],
               g_wpw_h[q], g_wpw_l[q]);
    }
}

// ---------------- K1: reduce 1x1 (256->128) + BN + SiLU via mma.sync bf16x3 ----------------
__global__ void __launch_bounds__(256, 1)
k_reduce_mma(const float* __restrict__ x, const float* __restrict__ bnr) {
    extern __shared__ char sm[];
    const int b = blockIdx.y;
    const int p0 = blockIdx.x * 128;
    const int tid = threadIdx.x;
    const int wid = tid >> 5;
    const int lane = tid & 31;
    const int g = lane >> 2, t = lane & 3;
    const int warp_m = wid >> 1;
    const int warp_n = wid & 1;

    float c[2][8][4];
#pragma unroll
    for (int mf = 0; mf < 2; mf++)
#pragma unroll
        for (int nf = 0; nf < 8; nf++)
#pragma unroll
            for (int i = 0; i < 4; i++) c[mf][nf][i] = 0.f;

    const float* xb = x + (size_t)b * C1 * HW + p0;

    for (int kc = 0; kc < 4; kc++) {
#pragma unroll
        for (int i = 0; i < 16; i++) {
            int p = i * 256 + tid;
            int oc = p >> 5, j = p & 31;
            int q = oc * 128 + kc * 32 + j;
            *(uint32_t*)(sm + OFF_A_HI + oc * TSTRIDE + j * 4) = g_wred_h[q];
            *(uint32_t*)(sm + OFF_A_LO + oc * TSTRIDE + j * 4) = g_wred_l[q];
        }
#pragma unroll
        for (int i = 0; i < 16; i++) {
            int p = i * 256 + tid;
            int px = p & 127, kp = p >> 7;
            const float* src = xb + (size_t)(kc * 64 + 2 * kp) * HW + px;
            uint32_t hi, lo;
            split2(src[0], src[HW], hi, lo);
            *(uint32_t*)(sm + OFF_B_HI + px * TSTRIDE + kp * 4) = hi;
            *(uint32_t*)(sm + OFF_B_LO + px * TSTRIDE + kp * 4) = lo;
        }
        __syncthreads();
#pragma unroll
        for (int ks = 0; ks < 4; ks++) {
            const int kk = ks * 16;
            uint32_t ahi[2][4], alo[2][4];
#pragma unroll
            for (int mf = 0; mf < 2; mf++) {
                int r0 = warp_m * 32 + mf * 16;
                const char* ph = sm + OFF_A_HI + (r0 + g) * TSTRIDE + (kk + 2 * t) * 2;
                ahi[mf][0] = *(const uint32_t*)(ph);
                ahi[mf][1] = *(const uint32_t*)(ph + 8 * TSTRIDE);
                ahi[mf][2] = *(const uint32_t*)(ph + 16);
                ahi[mf][3] = *(const uint32_t*)(ph + 8 * TSTRIDE + 16);
                const char* pl = sm + OFF_A_LO + (r0 + g) * TSTRIDE + (kk + 2 * t) * 2;
                alo[mf][0] = *(const uint32_t*)(pl);
                alo[mf][1] = *(const uint32_t*)(pl + 8 * TSTRIDE);
                alo[mf][2] = *(const uint32_t*)(pl + 16);
                alo[mf][3] = *(const uint32_t*)(pl + 8 * TSTRIDE + 16);
            }
            uint32_t bhi[8][2], blo[8][2];
#pragma unroll
            for (int nf = 0; nf < 8; nf++) {
                int n0 = warp_n * 64 + nf * 8;
                const char* ph = sm + OFF_B_HI + (n0 + g) * TSTRIDE + (kk + 2 * t) * 2;
                bhi[nf][0] = *(const uint32_t*)(ph);
                bhi[nf][1] = *(const uint32_t*)(ph + 16);
                const char* pl = sm + OFF_B_LO + (n0 + g) * TSTRIDE + (kk + 2 * t) * 2;
                blo[nf][0] = *(const uint32_t*)(pl);
                blo[nf][1] = *(const uint32_t*)(pl + 16);
            }
#pragma unroll
            for (int mf = 0; mf < 2; mf++)
#pragma unroll
                for (int nf = 0; nf < 8; nf++) {
                    mma16816(c[mf][nf], ahi[mf], bhi[nf]);
                    mma16816(c[mf][nf], ahi[mf], blo[nf]);
                    mma16816(c[mf][nf], alo[mf], bhi[nf]);
                }
        }
        __syncthreads();
    }

#pragma unroll
    for (int mf = 0; mf < 2; mf++) {
        int ocA = warp_m * 32 + mf * 16 + g;
        int ocB = ocA + 8;
        float gA = bnr[ocA], bA = bnr[128 + ocA], mA = bnr[256 + ocA], vA = bnr[384 + ocA];
        float sA = gA * rsqrtf(vA + 1e-5f), shA = bA - mA * sA;
        float gB = bnr[ocB], bB = bnr[128 + ocB], mB = bnr[256 + ocB], vB = bnr[384 + ocB];
        float sB = gB * rsqrtf(vB + 1e-5f), shB = bB - mB * sB;
        float* dA = g_h + ((size_t)b * CMID + ocA) * HW + p0 + warp_n * 64;
        float* dB = g_h + ((size_t)b * CMID + ocB) * HW + p0 + warp_n * 64;
#pragma unroll
        for (int nf = 0; nf < 8; nf++) {
            int px = nf * 8 + 2 * t;
            *(float2*)(dA + px) = make_float2(siluf(c[mf][nf][0] * sA + shA),
                                              siluf(c[mf][nf][1] * sA + shA));
            *(float2*)(dB + px) = make_float2(siluf(c[mf][nf][2] * sB + shB),
                                              siluf(c[mf][nf][3] * sB + shB));
        }
    }
}

// ---------------- K2: offset conv 3x3 (8-ch group partials) ----------------
__global__ void __launch_bounds__(256)
k_offconv_t(const float* __restrict__ wo) {
    __shared__ float tile[18][82];
    __shared__ float sw[3][8][9];
    const int grp = blockIdx.x;
    const int y0 = blockIdx.y * 16;
    const int b = blockIdx.z;
    const int tid = threadIdx.x;
    const int r = tid >> 4;
    const int xg = (tid & 15) * 5;

    if (tid < 3 * 8 * 9) {
        int o = tid / 72, rest = tid % 72;
        int cc = rest / 9, k = rest % 9;
        sw[o][cc][k] = wo[o * 576 + (grp * 8 + cc) * 9 + k];
    }

    float acc[3][5];
#pragma unroll
    for (int o = 0; o < 3; o++)
#pragma unroll
        for (int i = 0; i < 5; i++) acc[o][i] = 0.f;

    __syncthreads();
    for (int cc = 0; cc < 8; cc++) {
        const float* im = g_h + ((size_t)b * CMID + grp * 8 + cc) * HW;
        for (int i = tid; i < 18 * 82; i += 256) {
            int rr = i / 82, col = i % 82;
            int gy = y0 - 1 + rr, gx = col - 1;
            float v = 0.f;
            if (gy >= 0 && gy < HH && gx >= 0 && gx < WW) v = im[gy * WW + gx];
            tile[rr][col] = v;
        }
        __syncthreads();
#pragma unroll
        for (int i = 0; i < 5; i++) {
            float s[9];
#pragma unroll
            for (int ky = 0; ky < 3; ky++)
#pragma unroll
                for (int kx = 0; kx < 3; kx++)
                    s[ky * 3 + kx] = tile[r + ky][xg + i + kx];
#pragma unroll
            for (int o = 0; o < 3; o++)
#pragma unroll
                for (int k = 0; k < 9; k++)
                    acc[o][i] = fmaf(sw[o][cc][k], s[k], acc[o][i]);
        }
        __syncthreads();
    }
    float* dst = g_omp + ((size_t)grp * BB + b) * 3 * HW;
#pragma unroll
    for (int o = 0; o < 3; o++)
#pragma unroll
        for (int i = 0; i < 5; i++)
            dst[o * HW + (y0 + r) * WW + xg + i] = acc[o][i];
}

// ---------------- K3: sum offset partials + bake sampling params ----------------
__global__ void __launch_bounds__(256)
k_omsum(const float* __restrict__ bo) {
    const int p = blockIdx.x * 256 + threadIdx.x;
    const int b = blockIdx.y;
    const int xx = p % WW, yy = p / WW;

    float om0 = bo[0], om1 = bo[1], om2 = bo[2];
#pragma unroll
    for (int grp = 0; grp < 8; grp++) {
        const float* src = g_omp + ((size_t)grp * BB + b) * 3 * HW + p;
        om0 += src[0];
        om1 += src[HW];
        om2 += src[2 * HW];
    }
    float mk = sigf(om2);
    float linx = -1.f + 2.f * xx / (WW - 1);
    float liny = -1.f + 2.f * yy / (HH - 1);
    float gx = (linx + om1 * (2.f / WW) + 1.f) * 0.5f * (WW - 1);
    float gy = (liny + om0 * (2.f / HH) + 1.f) * 0.5f * (HH - 1);
    float x0f = floorf(gx), y0f = floorf(gy);
    float wx = gx - x0f, wy = gy - y0f;
    int x0 = (int)x0f, y0 = (int)y0f;
    bool vx0 = (x0 >= 0 && x0 < WW), vx1 = (x0 + 1 >= 0 && x0 + 1 < WW);
    bool vy0 = (y0 >= 0 && y0 < HH), vy1 = (y0 + 1 >= 0 && y0 + 1 < HH);
    int cx0 = min(max(x0, 0), WW - 1), cx1 = min(max(x0 + 1, 0), WW - 1);
    int cy0 = min(max(y0, 0), HH - 1), cy1 = min(max(y0 + 1, 0), HH - 1);
    float4 w;
    w.x = (1.f - wx) * (1.f - wy) * mk * (vx0 && vy0 ? 1.f : 0.f);
    w.y = wx * (1.f - wy) * mk * (vx1 && vy0 ? 1.f : 0.f);
    w.z = (1.f - wx) * wy * mk * (vx0 && vy1 ? 1.f : 0.f);
    w.w = wx * wy * mk * (vx1 && vy1 ? 1.f : 0.f);
    int4 ix;
    ix.x = cy0 * WW + cx0;
    ix.y = cy0 * WW + cx1;
    ix.z = cy1 * WW + cx0;
    ix.w = cy1 * WW + cx1;
    g_spw[(size_t)b * HW + p] = w;
    g_spi[(size_t)b * HW + p] = ix;
}

// ---------------- K4: fused grid-sample + depthwise 3x3 -> g_t1 ----------------
// grid (5 row-tiles, BB*CS), block 256
__global__ void __launch_bounds__(256)
k_sdw(const float* __restrict__ wdw) {
    __shared__ float tile[18][82];
    const int y0 = blockIdx.x * 16;
    const int bc = blockIdx.y;
    const int b = bc >> 6, c = bc & 63;
    const int tid = threadIdx.x;
    const int r = tid >> 4;
    const int xg = (tid & 15) * 5;

    const float* im = g_h + ((size_t)b * CMID + c) * HW;
    const float4* spw = g_spw + (size_t)b * HW;
    const int4* spi = g_spi + (size_t)b * HW;
    for (int i = tid; i < 18 * 82; i += 256) {
        int rr = i / 82, col = i % 82;
        int gy = y0 - 1 + rr, gx = col - 1;
        float v = 0.f;
        if (gy >= 0 && gy < HH && gx >= 0 && gx < WW) {
            int p = gy * WW + gx;
            float4 w = spw[p];
            int4 ix = spi[p];
            v = w.x * im[ix.x] + w.y * im[ix.y] + w.z * im[ix.z] + w.w * im[ix.w];
        }
        tile[rr][col] = v;
    }
    float w[9];
#pragma unroll
    for (int k = 0; k < 9; k++) w[k] = wdw[c * 9 + k];
    __syncthreads();

    float acc[5] = {0.f, 0.f, 0.f, 0.f, 0.f};
#pragma unroll
    for (int ky = 0; ky < 3; ky++) {
        float s[7];
#pragma unroll
        for (int j = 0; j < 7; j++) s[j] = tile[r + ky][xg + j];
#pragma unroll
        for (int i = 0; i < 5; i++)
#pragma unroll
            for (int kx = 0; kx < 3; kx++)
                acc[i] = fmaf(w[ky * 3 + kx], s[i + kx], acc[i]);
    }
    float* dst = g_t1 + (size_t)bc * HW + (y0 + r) * WW + xg;
#pragma unroll
    for (int i = 0; i < 5; i++) dst[i] = acc[i];
}

// ---------------- K5: pw 1x1 (64->64) + BN + SiLU via mma.sync bf16x3 ----------------
__global__ void __launch_bounds__(256, 1)
k_pw_mma(const float* __restrict__ bnp) {
    extern __shared__ char sm[];
    const int b = blockIdx.y;
    const int p0 = blockIdx.x * 128;
    const int tid = threadIdx.x;
    const int wid = tid >> 5;
    const int lane = tid & 31;
    const int g = lane >> 2, t = lane & 3;
    const int warp_m = wid >> 2;
    const int warp_n = wid & 3;

    float c[2][4][4];
#pragma unroll
    for (int mf = 0; mf < 2; mf++)
#pragma unroll
        for (int nf = 0; nf < 4; nf++)
#pragma unroll
            for (int i = 0; i < 4; i++) c[mf][nf][i] = 0.f;

#pragma unroll
    for (int i = 0; i < 8; i++) {
        int p = i * 256 + tid;
        int oc = p >> 5, j = p & 31;
        *(uint32_t*)(sm + PW_A_HI + oc * TSTRIDE + j * 4) = g_wpw_h[p];
        *(uint32_t*)(sm + PW_A_LO + oc * TSTRIDE + j * 4) = g_wpw_l[p];
    }
    const float* tb = g_t1 + (size_t)b * CS * HW + p0;
#pragma unroll
    for (int i = 0; i < 16; i++) {
        int p = i * 256 + tid;
        int px = p & 127, kp = p >> 7;
        const float* src = tb + (size_t)(2 * kp) * HW + px;
        uint32_t hi, lo;
        split2(src[0], src[HW], hi, lo);
        *(uint32_t*)(sm + PW_B_HI + px * TSTRIDE + kp * 4) = hi;
        *(uint32_t*)(sm + PW_B_LO + px * TSTRIDE + kp * 4) = lo;
    }
    __syncthreads();
#pragma unroll
    for (int ks = 0; ks < 4; ks++) {
        const int kk = ks * 16;
        uint32_t ahi[2][4], alo[2][4];
#pragma unroll
        for (int mf = 0; mf < 2; mf++) {
            int r0 = warp_m * 32 + mf * 16;
            const char* ph = sm + PW_A_HI + (r0 + g) * TSTRIDE + (kk + 2 * t) * 2;
            ahi[mf][0] = *(const uint32_t*)(ph);
            ahi[mf][1] = *(const uint32_t*)(ph + 8 * TSTRIDE);
            ahi[mf][2] = *(const uint32_t*)(ph + 16);
            ahi[mf][3] = *(const uint32_t*)(ph + 8 * TSTRIDE + 16);
            const char* pl = sm + PW_A_LO + (r0 + g) * TSTRIDE + (kk + 2 * t) * 2;
            alo[mf][0] = *(const uint32_t*)(pl);
            alo[mf][1] = *(const uint32_t*)(pl + 8 * TSTRIDE);
            alo[mf][2] = *(const uint32_t*)(pl + 16);
            alo[mf][3] = *(const uint32_t*)(pl + 8 * TSTRIDE + 16);
        }
        uint32_t bhi[4][2], blo[4][2];
#pragma unroll
        for (int nf = 0; nf < 4; nf++) {
            int n0 = warp_n * 32 + nf * 8;
            const char* ph = sm + PW_B_HI + (n0 + g) * TSTRIDE + (kk + 2 * t) * 2;
            bhi[nf][0] = *(const uint32_t*)(ph);
            bhi[nf][1] = *(const uint32_t*)(ph + 16);
            const char* pl = sm + PW_B_LO + (n0 + g) * TSTRIDE + (kk + 2 * t) * 2;
            blo[nf][0] = *(const uint32_t*)(pl);
            blo[nf][1] = *(const uint32_t*)(pl + 16);
        }
#pragma unroll
        for (int mf = 0; mf < 2; mf++)
#pragma unroll
            for (int nf = 0; nf < 4; nf++) {
                mma16816(c[mf][nf], ahi[mf], bhi[nf]);
                mma16816(c[mf][nf], ahi[mf], blo[nf]);
                mma16816(c[mf][nf], alo[mf], bhi[nf]);
            }
    }

#pragma unroll
    for (int mf = 0; mf < 2; mf++) {
        int ocA = warp_m * 32 + mf * 16 + g;
        int ocB = ocA + 8;
        float gA = bnp[ocA], bA = bnp[64 + ocA], mA = bnp[128 + ocA], vA = bnp[192 + ocA];
        float sA = gA * rsqrtf(vA + 1e-5f), shA = bA - mA * sA;
        float gB = bnp[ocB], bB = bnp[64 + ocB], mB = bnp[128 + ocB], vB = bnp[192 + ocB];
        float sB = gB * rsqrtf(vB + 1e-5f), shB = bB - mB * sB;
        float* dA = g_dcn + ((size_t)b * CS + ocA) * HW + p0 + warp_n * 32;
        float* dB = g_dcn + ((size_t)b * CS + ocB) * HW + p0 + warp_n * 32;
#pragma unroll
        for (int nf = 0; nf < 4; nf++) {
            int px = nf * 8 + 2 * t;
            *(float2*)(dA + px) = make_float2(siluf(c[mf][nf][0] * sA + shA),
                                              siluf(c[mf][nf][1] * sA + shA));
            *(float2*)(dB + px) = make_float2(siluf(c[mf][nf][2] * sB + shB),
                                              siluf(c[mf][nf][3] * sB + shB));
        }
    }
}

// ---------------- K6: fused d2 + d3 + asym1 + asym2 + ctx blend + star + chmean ----------------
__global__ void __launch_bounds__(256)
k_ctx_star(const float* __restrict__ wd2, const float* __restrict__ bnd2,
           const float* __restrict__ wd3, const float* __restrict__ bnd3,
           const float* __restrict__ wa1, const float* __restrict__ bna1,
           const float* __restrict__ wa2, const float* __restrict__ bna2,
           const float* __restrict__ cw, const float* __restrict__ bns) {
    __shared__ float hst[22][86];
    __shared__ float sa1[22][80];
    __shared__ float ssum[256];
    const int y0 = blockIdx.x * 16;
    const int bc = blockIdx.y;
    const int b = bc >> 6, c = bc & 63;
    const int tid = threadIdx.x;
    const int r = tid >> 4;
    const int xg = (tid & 15) * 5;

    const float* im = g_h + ((size_t)b * CMID + c) * HW;
    for (int i = tid; i < 22 * 86; i += 256) {
        int rr = i / 86, col = i % 86;
        int gy = y0 - 3 + rr, gx = col - 3;
        float v = 0.f;
        if (gy >= 0 && gy < HH && gx >= 0 && gx < WW) v = im[gy * WW + gx];
        hst[rr][col] = v;
    }
    float wa1r[7], wa2r[7], wd2r[9], wd3r[9];
#pragma unroll
    for (int k = 0; k < 7; k++) { wa1r[k] = wa1[c * 7 + k]; wa2r[k] = wa2[c * 7 + k]; }
#pragma unroll
    for (int k = 0; k < 9; k++) { wd2r[k] = wd2[c * 9 + k]; wd3r[k] = wd3[c * 9 + k]; }
    float sA1 = bna1[c] * rsqrtf(bna1[192 + c] + 1e-5f);
    float hA1 = bna1[64 + c] - bna1[128 + c] * sA1;
    float sA2 = bna2[c] * rsqrtf(bna2[192 + c] + 1e-5f);
    float hA2 = bna2[64 + c] - bna2[128 + c] * sA2;
    float sD2 = bnd2[c] * rsqrtf(bnd2[192 + c] + 1e-5f);
    float hD2 = bnd2[64 + c] - bnd2[128 + c] * sD2;
    float sD3 = bnd3[c] * rsqrtf(bnd3[192 + c] + 1e-5f);
    float hD3 = bnd3[64 + c] - bnd3[128 + c] * sD3;
    float sST = bns[c] * rsqrtf(bns[192 + c] + 1e-5f);
    float hST = bns[64 + c] - bns[128 + c] * sST;
    float e0 = __expf(cw[0]), e1 = __expf(cw[1]), e2 = __expf(cw[2]);
    float inv = 1.f / (e0 + e1 + e2);
    float cw0 = e0 * inv, cw1 = e1 * inv, cw2 = e2 * inv;
    __syncthreads();

    for (int i = tid; i < 22 * 80; i += 256) {
        int rr = i / 80, col = i % 80;
        int gy = y0 - 3 + rr;
        float v = 0.f;
        if (gy >= 0 && gy < HH) {
            float a = 0.f;
#pragma unroll
            for (int k = 0; k < 7; k++) a = fmaf(wa1r[k], hst[rr][col + k], a);
            v = siluf(a * sA1 + hA1);
        }
        sa1[rr][col] = v;
    }
    __syncthreads();

    const float* dcnp = g_dcn + (size_t)bc * HW;
    float* starp = g_star + (size_t)bc * HW;
    float lsum = 0.f;
#pragma unroll
    for (int i = 0; i < 5; i++) {
        int col = xg + i;
        float d2 = 0.f, d3 = 0.f;
#pragma unroll
        for (int ky = 0; ky < 3; ky++)
#pragma unroll
            for (int kx = 0; kx < 3; kx++) {
                d2 = fmaf(wd2r[ky * 3 + kx], hst[r + 3 + 2 * (ky - 1)][col + 3 + 2 * (kx - 1)], d2);
                d3 = fmaf(wd3r[ky * 3 + kx], hst[r + 3 + 3 * (ky - 1)][col + 3 + 3 * (kx - 1)], d3);
            }
        float a2 = 0.f;
#pragma unroll
        for (int ky = 0; ky < 7; ky++) a2 = fmaf(wa2r[ky], sa1[r + ky][col], a2);
        float ctx = cw0 * siluf(d2 * sD2 + hD2)
                  + cw1 * siluf(d3 * sD3 + hD3)
                  + cw2 * siluf(a2 * sA2 + hA2);
        int p = (y0 + r) * WW + col;
        float st = (dcnp[p] * ctx) * sST + hST;
        starp[p] = st;
        lsum += st;
    }
    ssum[tid] = lsum;
    __syncthreads();
    for (int o = 128; o > 0; o >>= 1) {
        if (tid < o) ssum[tid] += ssum[tid + o];
        __syncthreads();
    }
    if (tid == 0) atomicAdd(&g_chmean[bc], ssum[0]);
}

// ---------------- K7: ECA conv1d(k=5,pad=2) + sigmoid ----------------
__global__ void k_eca(const float* __restrict__ ew) {
    int b = blockIdx.x;
    int c = threadIdx.x;
    __shared__ float sm[CS];
    sm[c] = g_chmean[b * CS + c] * (1.f / (float)HW);
    __syncthreads();
    float s = 0.f;
#pragma unroll
    for (int k = 0; k < 5; k++) {
        int cc = c - 2 + k;
        if (cc >= 0 && cc < CS) s = fmaf(ew[k], sm[cc], s);
    }
    g_ych[b * CS + c] = sigf(s);
}

// ---------------- K8: spatial mean/max (channel-quad split) ----------------
__global__ void __launch_bounds__(256)
k_spstat() {
    __shared__ float ys[CS];
    __shared__ float smean[4][64];
    __shared__ float smax[4][64];
    const int b = blockIdx.y;
    const int px = threadIdx.x & 63;
    const int q = threadIdx.x >> 6;
    const int p = blockIdx.x * 64 + px;
    if (threadIdx.x < CS) ys[threadIdx.x] = g_ych[b * CS + threadIdx.x];
    __syncthreads();
    float s = 0.f, mx = -3.4e38f;
    const float* base = g_star + ((size_t)b * CS + q * 16) * HW + p;
#pragma unroll 4
    for (int c = 0; c < 16; c++) {
        float v = base[(size_t)c * HW] * ys[q * 16 + c];
        s += v;
        mx = fmaxf(mx, v);
    }
    smean[q][px] = s;
    smax[q][px] = mx;
    __syncthreads();
    if (q == 0) {
#pragma unroll
        for (int k = 1; k < 4; k++) {
            s += smean[k][px];
            mx = fmaxf(mx, smax[k][px]);
        }
        g_spmean[(size_t)b * HW + p] = s * (1.f / (float)CS);
        g_spmax[(size_t)b * HW + p] = mx;
    }
}

// ---------------- K9: spatial attention conv 7x7 (2->1) + sigmoid (tiled) ----------------
__global__ void __launch_bounds__(256)
k_satt_t(const float* __restrict__ sw) {
    __shared__ float m0t[22][86];
    __shared__ float m1t[22][86];
    const int y0 = blockIdx.x * 16;
    const int b = blockIdx.y;
    const int tid = threadIdx.x;
    const int r = tid >> 4;
    const int xg = (tid & 15) * 5;

    const float* m0 = g_spmean + (size_t)b * HW;
    const float* m1 = g_spmax + (size_t)b * HW;
    for (int i = tid; i < 22 * 86; i += 256) {
        int rr = i / 86, col = i % 86;
        int gy = y0 - 3 + rr, gx = col - 3;
        float v0 = 0.f, v1 = 0.f;
        if (gy >= 0 && gy < HH && gx >= 0 && gx < WW) {
            v0 = m0[gy * WW + gx];
            v1 = m1[gy * WW + gx];
        }
        m0t[rr][col] = v0;
        m1t[rr][col] = v1;
    }
    __syncthreads();
    float* dst = g_satt + (size_t)b * HW + (y0 + r) * WW + xg;
#pragma unroll
    for (int i = 0; i < 5; i++) {
        float s = 0.f;
#pragma unroll
        for (int ky = 0; ky < 7; ky++)
#pragma unroll
            for (int kx = 0; kx < 7; kx++) {
                s = fmaf(sw[ky * 7 + kx], m0t[r + ky][xg + i + kx], s);
                s = fmaf(sw[49 + ky * 7 + kx], m1t[r + ky][xg + i + kx], s);
            }
        dst[i] = sigf(s);
    }
}

// ---------------- K10: expand 1x1 (128->256) + BN + SiLU + residual via mma.sync ----------------
__global__ void __launch_bounds__(256, 1)
k_expand_mma(const float* __restrict__ x, const float* __restrict__ bne,
             const float* __restrict__ bw, float* __restrict__ out) {
    extern __shared__ char sm[];
    const int b = blockIdx.y;
    const int p0 = blockIdx.x * 128;
    const int oc0 = blockIdx.z * 128;
    const int tid = threadIdx.x;
    const int wid = tid >> 5;
    const int lane = tid & 31;
    const int g = lane >> 2, t = lane & 3;
    const int warp_m = wid >> 1;
    const int warp_n = wid & 1;

    const float alpha = 1.f / (1.f + __expf(-bw[0]));
    const float oma = 1.f - alpha;

    float c[2][8][4];
#pragma unroll
    for (int mf = 0; mf < 2; mf++)
#pragma unroll
        for (int nf = 0; nf < 8; nf++)
#pragma unroll
            for (int i = 0; i < 4; i++) c[mf][nf][i] = 0.f;

    for (int kc = 0; kc < 2; kc++) {
#pragma unroll
        for (int i = 0; i < 16; i++) {
            int p = i * 256 + tid;
            int oc = p >> 5, j = p & 31;
            int q = (oc0 + oc) * 64 + kc * 32 + j;
            *(uint32_t*)(sm + OFF_A_HI + oc * TSTRIDE + j * 4) = g_wexp_h[q];
            *(uint32_t*)(sm + OFF_A_LO + oc * TSTRIDE + j * 4) = g_wexp_l[q];
        }
#pragma unroll
        for (int i = 0; i < 16; i++) {
            int p = i * 256 + tid;
            int px = p & 127, kp = p >> 7;
            int ch = kc * 32 + kp;
            float v0 = g_star[((size_t)b * CS + ch) * HW + p0 + px]
                     * g_ych[b * CS + ch]
                     * g_satt[(size_t)b * HW + p0 + px] * alpha;
            float v1 = g_h[((size_t)b * CMID + CS + ch) * HW + p0 + px] * oma;
            uint32_t hi, lo;
            split2(v0, v1, hi, lo);
            *(uint32_t*)(sm + OFF_B_HI + px * TSTRIDE + kp * 4) = hi;
            *(uint32_t*)(sm + OFF_B_LO + px * TSTRIDE + kp * 4) = lo;
        }
        __syncthreads();
#pragma unroll
        for (int ks = 0; ks < 4; ks++) {
            const int kk = ks * 16;
            uint32_t ahi[2][4], alo[2][4];
#pragma unroll
            for (int mf = 0; mf < 2; mf++) {
                int r0 = warp_m * 32 + mf * 16;
                const char* ph = sm + OFF_A_HI + (r0 + g) * TSTRIDE + (kk + 2 * t) * 2;
                ahi[mf][0] = *(const uint32_t*)(ph);
                ahi[mf][1] = *(const uint32_t*)(ph + 8 * TSTRIDE);
                ahi[mf][2] = *(const uint32_t*)(ph + 16);
                ahi[mf][3] = *(const uint32_t*)(ph + 8 * TSTRIDE + 16);
                const char* pl = sm + OFF_A_LO + (r0 + g) * TSTRIDE + (kk + 2 * t) * 2;
                alo[mf][0] = *(const uint32_t*)(pl);
                alo[mf][1] = *(const uint32_t*)(pl + 8 * TSTRIDE);
                alo[mf][2] = *(const uint32_t*)(pl + 16);
                alo[mf][3] = *(const uint32_t*)(pl + 8 * TSTRIDE + 16);
            }
            uint32_t bhi[8][2], blo[8][2];
#pragma unroll
            for (int nf = 0; nf < 8; nf++) {
                int n0 = warp_n * 64 + nf * 8;
                const char* ph = sm + OFF_B_HI + (n0 + g) * TSTRIDE + (kk + 2 * t) * 2;
                bhi[nf][0] = *(const uint32_t*)(ph);
                bhi[nf][1] = *(const uint32_t*)(ph + 16);
                const char* pl = sm + OFF_B_LO + (n0 + g) * TSTRIDE + (kk + 2 * t) * 2;
                blo[nf][0] = *(const uint32_t*)(pl);
                blo[nf][1] = *(const uint32_t*)(pl + 16);
            }
#pragma unroll
            for (int mf = 0; mf < 2; mf++)
#pragma unroll
                for (int nf = 0; nf < 8; nf++) {
                    mma16816(c[mf][nf], ahi[mf], bhi[nf]);
                    mma16816(c[mf][nf], ahi[mf], blo[nf]);
                    mma16816(c[mf][nf], alo[mf], bhi[nf]);
                }
        }
        __syncthreads();
    }

#pragma unroll
    for (int mf = 0; mf < 2; mf++) {
        int ocA = oc0 + warp_m * 32 + mf * 16 + g;
        int ocB = ocA + 8;
        float gA = bne[ocA], bA = bne[256 + ocA], mA = bne[512 + ocA], vA = bne[768 + ocA];
        float sA = gA * rsqrtf(vA + 1e-5f), shA = bA - mA * sA;
        float gB = bne[ocB], bB = bne[256 + ocB], mB = bne[512 + ocB], vB = bne[768 + ocB];
        float sB = gB * rsqrtf(vB + 1e-5f), shB = bB - mB * sB;
        float* dA = out + ((size_t)b * C1 + ocA) * HW + p0 + warp_n * 64;
        float* dB = out + ((size_t)b * C1 + ocB) * HW + p0 + warp_n * 64;
        const float* rA = x + ((size_t)b * C1 + ocA) * HW + p0 + warp_n * 64;
        const float* rB = x + ((size_t)b * C1 + ocB) * HW + p0 + warp_n * 64;
#pragma unroll
        for (int nf = 0; nf < 8; nf++) {
            int px = nf * 8 + 2 * t;
            float2 resA = *(const float2*)(rA + px);
            float2 resB = *(const float2*)(rB + px);
            *(float2*)(dA + px) = make_float2(siluf(c[mf][nf][0] * sA + shA) + resA.x,
                                              siluf(c[mf][nf][1] * sA + shA) + resA.y);
            *(float2*)(dB + px) = make_float2(siluf(c[mf][nf][2] * sB + shB) + resB.x,
                                              siluf(c[mf][nf][3] * sB + shB) + resB.y);
        }
    }
}

// ---------------- launch ----------------
extern "C" void kernel_launch(void* const* d_in, const int* in_sizes, int n_in,
                              void* d_out, int out_size) {
    const float* x          = (const float*)d_in[0];
    const float* w_reduce   = (const float*)d_in[1];
    const float* bn_reduce  = (const float*)d_in[2];
    const float* dcn_off_w  = (const float*)d_in[3];
    const float* dcn_off_b  = (const float*)d_in[4];
    const float* dcn_dw_w   = (const float*)d_in[5];
    const float* dcn_pw_w   = (const float*)d_in[6];
    const float* bn_dcn     = (const float*)d_in[7];
    const float* w_d2       = (const float*)d_in[8];
    const float* bn_d2      = (const float*)d_in[9];
    const float* w_d3       = (const float*)d_in[10];
    const float* bn_d3      = (const float*)d_in[11];
    const float* w_asym1    = (const float*)d_in[12];
    const float* bn_asym1   = (const float*)d_in[13];
    const float* w_asym2    = (const float*)d_in[14];
    const float* bn_asym2   = (const float*)d_in[15];
    const float* ctx_weight = (const float*)d_in[16];
    const float* bn_star    = (const float*)d_in[17];
    const float* eca_w      = (const float*)d_in[18];
    const float* sp_w       = (const float*)d_in[19];
    const float* blend_w    = (const float*)d_in[20];
    const float* w_expand   = (const float*)d_in[21];
    const float* bn_expand  = (const float*)d_in[22];
    float* out = (float*)d_out;

    static bool attr_done = false;
    if (!attr_done) {
        cudaFuncSetAttribute(k_reduce_mma, cudaFuncAttributeMaxDynamicSharedMemorySize, GEMM_SMEM);
        cudaFuncSetAttribute(k_expand_mma, cudaFuncAttributeMaxDynamicSharedMemorySize, GEMM_SMEM);
        cudaFuncSetAttribute(k_pw_mma, cudaFuncAttributeMaxDynamicSharedMemorySize, PW_SMEM);
        attr_done = true;
    }

    k_zero<<<4, 256>>>();
    k_prepw<<<136, 256>>>(w_reduce, w_expand, dcn_pw_w);
    k_reduce_mma<<<dim3(HW / 128, BB), 256, GEMM_SMEM>>>(x, bn_reduce);
    k_offconv_t<<<dim3(8, 5, BB), 256>>>(dcn_off_w);
    k_omsum<<<dim3(HW / 256, BB), 256>>>(dcn_off_b);
    k_sdw<<<dim3(5, BB * CS), 256>>>(dcn_dw_w);
    k_pw_mma<<<dim3(HW / 128, BB), 256, PW_SMEM>>>(bn_dcn);
    k_ctx_star<<<dim3(5, BB * CS), 256>>>(w_d2, bn_d2, w_d3, bn_d3,
                                          w_asym1, bn_asym1, w_asym2, bn_asym2,
                                          ctx_weight, bn_star);
    k_eca<<<BB, CS>>>(eca_w);
    k_spstat<<<dim3(HW / 64, BB), 256>>>();
    k_satt_t<<<dim3(5, BB), 256>>>(sp_w);
    k_expand_mma<<<dim3(HW / 128, BB, 2), 256, GEMM_SMEM>>>(x, bn_expand, blend_w, out);
}

// round 9
// speedup vs baseline: 1.4016x; 1.4016x over previous
#include <cuda_runtime.h>
#include <cuda_bf16.h>
#include <cstdint>

#define BB 16
#define C1 256
#define CMID 128
#define CS 64
#define HH 80
#define WW 80
#define HW 6400
#define NGRP 16

// ---------------- scratch (device globals; no allocations) ----------------
__device__ float g_h[(size_t)BB*CMID*HW];     // reduce output (hs ch 0..63, hb 64..127)
__device__ float g_omp[(size_t)NGRP*BB*3*HW]; // offset conv partials (16 channel groups)
__device__ float4 g_spw[(size_t)BB*HW];       // bilinear weights (mask folded)
__device__ int4   g_spi[(size_t)BB*HW];       // gather indices (clamped)
__device__ float g_xd[(size_t)BB*CS*HW];      // grid-sampled * mask
__device__ float g_t1[(size_t)BB*CS*HW];      // dcn depthwise out
__device__ float g_dcn[(size_t)BB*CS*HW];     // dcn branch
__device__ float g_star[(size_t)BB*CS*HW];    // star0 = bn_star(dcn*ctx)
__device__ float g_chmean[BB*CS];             // raw channel sums (atomic)
__device__ float g_ych[BB*CS];
__device__ float g_spmean[(size_t)BB*HW];
__device__ float g_spmax[(size_t)BB*HW];
__device__ float g_satt[(size_t)BB*HW];
// pre-split bf16 hi/lo weights (k-pair packed)
__device__ uint32_t g_wred_h[128*128], g_wred_l[128*128];
__device__ uint32_t g_wexp_h[256*64],  g_wexp_l[256*64];
__device__ uint32_t g_wpw_h[64*32],    g_wpw_l[64*32];

__device__ __forceinline__ float siluf(float v) { return v / (1.f + __expf(-v)); }
__device__ __forceinline__ float sigf(float v)  { return 1.f / (1.f + __expf(-v)); }

// ---------------- mma.sync helpers ----------------
__device__ __forceinline__ void mma16816(float* c, const uint32_t* a, const uint32_t* b) {
    asm volatile(
        "mma.sync.aligned.m16n8k16.row.col.f32.bf16.bf16.f32 "
        "{%0,%1,%2,%3}, {%4,%5,%6,%7}, {%8,%9}, {%0,%1,%2,%3};"
        : "+f"(c[0]), "+f"(c[1]), "+f"(c[2]), "+f"(c[3])
        : "r"(a[0]), "r"(a[1]), "r"(a[2]), "r"(a[3]), "r"(b[0]), "r"(b[1]));
}

__device__ __forceinline__ void split2(float v0, float v1, uint32_t& hi, uint32_t& lo) {
    __nv_bfloat16 h0 = __float2bfloat16(v0);
    __nv_bfloat16 h1 = __float2bfloat16(v1);
    __nv_bfloat16 l0 = __float2bfloat16(v0 - __bfloat162float(h0));
    __nv_bfloat16 l1 = __float2bfloat16(v1 - __bfloat162float(h1));
    __nv_bfloat162 th(h0, h1), tl(l0, l1);
    hi = *(uint32_t*)&th;
    lo = *(uint32_t*)&tl;
}

#define TSTRIDE 144
#define TILE_BYTES (128 * TSTRIDE)           // 18432
#define OFF_A_HI 0
#define OFF_A_LO TILE_BYTES
#define OFF_B_HI (2 * TILE_BYTES)
#define OFF_B_LO (3 * TILE_BYTES)
#define GEMM_SMEM (4 * TILE_BYTES)           // 73728

#define PW_A_HI 0
#define PW_A_LO (64 * TSTRIDE)
#define PW_B_HI (2 * 64 * TSTRIDE)
#define PW_B_LO (PW_B_HI + 128 * TSTRIDE)
#define PW_SMEM (PW_B_LO + 128 * TSTRIDE)    // 55296

// ---------------- K0: zero channel-sum accumulator ----------------
__global__ void k_zero() {
    g_chmean[blockIdx.x * 256 + threadIdx.x] = 0.f;
}

// ---------------- K0b: pre-split GEMM weights to bf16 hi/lo ----------------
__global__ void k_prepw(const float* __restrict__ wred, const float* __restrict__ wexp,
                        const float* __restrict__ wpw) {
    int idx = blockIdx.x * 256 + threadIdx.x;   // 0..34815
    if (idx < 16384) {
        int oc = idx >> 7, j = idx & 127;
        split2(wred[oc * 256 + 2 * j], wred[oc * 256 + 2 * j + 1],
               g_wred_h[idx], g_wred_l[idx]);
    } else if (idx < 32768) {
        int q = idx - 16384;
        int oc = q >> 6, j = q & 63;
        split2(wexp[oc * 128 + 2 * j], wexp[oc * 128 + 2 * j + 1],
               g_wexp_h[q], g_wexp_l[q]);
    } else {
        int q = idx - 32768;
        int oc = q >> 5, j = q & 31;
        split2(wpw[oc * 64 + 2 * j], wpw[oc * 64 + 2 * j + 1],
               g_wpw_h[q], g_wpw_l[q]);
    }
}

// ---------------- K1: reduce 1x1 (256->128) + BN + SiLU via mma.sync bf16x3 ----------------
__global__ void __launch_bounds__(256, 1)
k_reduce_mma(const float* __restrict__ x, const float* __restrict__ bnr) {
    extern __shared__ char sm[];
    const int b = blockIdx.y;
    const int p0 = blockIdx.x * 128;
    const int tid = threadIdx.x;
    const int wid = tid >> 5;
    const int lane = tid & 31;
    const int g = lane >> 2, t = lane & 3;
    const int warp_m = wid >> 1;
    const int warp_n = wid & 1;

    float c[2][8][4];
#pragma unroll
    for (int mf = 0; mf < 2; mf++)
#pragma unroll
        for (int nf = 0; nf < 8; nf++)
#pragma unroll
            for (int i = 0; i < 4; i++) c[mf][nf][i] = 0.f;

    const float* xb = x + (size_t)b * C1 * HW + p0;

    for (int kc = 0; kc < 4; kc++) {
#pragma unroll
        for (int i = 0; i < 16; i++) {
            int p = i * 256 + tid;
            int oc = p >> 5, j = p & 31;
            int q = oc * 128 + kc * 32 + j;
            *(uint32_t*)(sm + OFF_A_HI + oc * TSTRIDE + j * 4) = g_wred_h[q];
            *(uint32_t*)(sm + OFF_A_LO + oc * TSTRIDE + j * 4) = g_wred_l[q];
        }
#pragma unroll
        for (int i = 0; i < 16; i++) {
            int p = i * 256 + tid;
            int px = p & 127, kp = p >> 7;
            const float* src = xb + (size_t)(kc * 64 + 2 * kp) * HW + px;
            uint32_t hi, lo;
            split2(src[0], src[HW], hi, lo);
            *(uint32_t*)(sm + OFF_B_HI + px * TSTRIDE + kp * 4) = hi;
            *(uint32_t*)(sm + OFF_B_LO + px * TSTRIDE + kp * 4) = lo;
        }
        __syncthreads();
#pragma unroll
        for (int ks = 0; ks < 4; ks++) {
            const int kk = ks * 16;
            uint32_t ahi[2][4], alo[2][4];
#pragma unroll
            for (int mf = 0; mf < 2; mf++) {
                int r0 = warp_m * 32 + mf * 16;
                const char* ph = sm + OFF_A_HI + (r0 + g) * TSTRIDE + (kk + 2 * t) * 2;
                ahi[mf][0] = *(const uint32_t*)(ph);
                ahi[mf][1] = *(const uint32_t*)(ph + 8 * TSTRIDE);
                ahi[mf][2] = *(const uint32_t*)(ph + 16);
                ahi[mf][3] = *(const uint32_t*)(ph + 8 * TSTRIDE + 16);
                const char* pl = sm + OFF_A_LO + (r0 + g) * TSTRIDE + (kk + 2 * t) * 2;
                alo[mf][0] = *(const uint32_t*)(pl);
                alo[mf][1] = *(const uint32_t*)(pl + 8 * TSTRIDE);
                alo[mf][2] = *(const uint32_t*)(pl + 16);
                alo[mf][3] = *(const uint32_t*)(pl + 8 * TSTRIDE + 16);
            }
            uint32_t bhi[8][2], blo[8][2];
#pragma unroll
            for (int nf = 0; nf < 8; nf++) {
                int n0 = warp_n * 64 + nf * 8;
                const char* ph = sm + OFF_B_HI + (n0 + g) * TSTRIDE + (kk + 2 * t) * 2;
                bhi[nf][0] = *(const uint32_t*)(ph);
                bhi[nf][1] = *(const uint32_t*)(ph + 16);
                const char* pl = sm + OFF_B_LO + (n0 + g) * TSTRIDE + (kk + 2 * t) * 2;
                blo[nf][0] = *(const uint32_t*)(pl);
                blo[nf][1] = *(const uint32_t*)(pl + 16);
            }
#pragma unroll
            for (int mf = 0; mf < 2; mf++)
#pragma unroll
                for (int nf = 0; nf < 8; nf++) {
                    mma16816(c[mf][nf], ahi[mf], bhi[nf]);
                    mma16816(c[mf][nf], ahi[mf], blo[nf]);
                    mma16816(c[mf][nf], alo[mf], bhi[nf]);
                }
        }
        __syncthreads();
    }

#pragma unroll
    for (int mf = 0; mf < 2; mf++) {
        int ocA = warp_m * 32 + mf * 16 + g;
        int ocB = ocA + 8;
        float gA = bnr[ocA], bA = bnr[128 + ocA], mA = bnr[256 + ocA], vA = bnr[384 + ocA];
        float sA = gA * rsqrtf(vA + 1e-5f), shA = bA - mA * sA;
        float gB = bnr[ocB], bB = bnr[128 + ocB], mB = bnr[256 + ocB], vB = bnr[384 + ocB];
        float sB = gB * rsqrtf(vB + 1e-5f), shB = bB - mB * sB;
        float* dA = g_h + ((size_t)b * CMID + ocA) * HW + p0 + warp_n * 64;
        float* dB = g_h + ((size_t)b * CMID + ocB) * HW + p0 + warp_n * 64;
#pragma unroll
        for (int nf = 0; nf < 8; nf++) {
            int px = nf * 8 + 2 * t;
            *(float2*)(dA + px) = make_float2(siluf(c[mf][nf][0] * sA + shA),
                                              siluf(c[mf][nf][1] * sA + shA));
            *(float2*)(dB + px) = make_float2(siluf(c[mf][nf][2] * sB + shB),
                                              siluf(c[mf][nf][3] * sB + shB));
        }
    }
}

// ---------------- K2: offset conv 3x3 (4-ch group partials, 16 groups) ----------------
__global__ void __launch_bounds__(256)
k_offconv_t(const float* __restrict__ wo) {
    __shared__ float tile[18][82];
    __shared__ float sw[3][4][9];
    const int grp = blockIdx.x;
    const int y0 = blockIdx.y * 16;
    const int b = blockIdx.z;
    const int tid = threadIdx.x;
    const int r = tid >> 4;
    const int xg = (tid & 15) * 5;

    if (tid < 3 * 4 * 9) {
        int o = tid / 36, rest = tid % 36;
        int cc = rest / 9, k = rest % 9;
        sw[o][cc][k] = wo[o * 576 + (grp * 4 + cc) * 9 + k];
    }

    float acc[3][5];
#pragma unroll
    for (int o = 0; o < 3; o++)
#pragma unroll
        for (int i = 0; i < 5; i++) acc[o][i] = 0.f;

    __syncthreads();
    for (int cc = 0; cc < 4; cc++) {
        const float* im = g_h + ((size_t)b * CMID + grp * 4 + cc) * HW;
        for (int i = tid; i < 18 * 82; i += 256) {
            int rr = i / 82, col = i % 82;
            int gy = y0 - 1 + rr, gx = col - 1;
            float v = 0.f;
            if (gy >= 0 && gy < HH && gx >= 0 && gx < WW) v = im[gy * WW + gx];
            tile[rr][col] = v;
        }
        __syncthreads();
#pragma unroll
        for (int i = 0; i < 5; i++) {
            float s[9];
#pragma unroll
            for (int ky = 0; ky < 3; ky++)
#pragma unroll
                for (int kx = 0; kx < 3; kx++)
                    s[ky * 3 + kx] = tile[r + ky][xg + i + kx];
#pragma unroll
            for (int o = 0; o < 3; o++)
#pragma unroll
                for (int k = 0; k < 9; k++)
                    acc[o][i] = fmaf(sw[o][cc][k], s[k], acc[o][i]);
        }
        __syncthreads();
    }
    float* dst = g_omp + ((size_t)grp * BB + b) * 3 * HW;
#pragma unroll
    for (int o = 0; o < 3; o++)
#pragma unroll
        for (int i = 0; i < 5; i++)
            dst[o * HW + (y0 + r) * WW + xg + i] = acc[o][i];
}

// ---------------- K3: sum offset partials + bake sampling params ----------------
__global__ void __launch_bounds__(256)
k_omsum(const float* __restrict__ bo) {
    const int p = blockIdx.x * 256 + threadIdx.x;
    const int b = blockIdx.y;
    const int xx = p % WW, yy = p / WW;

    float om0 = bo[0], om1 = bo[1], om2 = bo[2];
#pragma unroll
    for (int grp = 0; grp < NGRP; grp++) {
        const float* src = g_omp + ((size_t)grp * BB + b) * 3 * HW + p;
        om0 += src[0];
        om1 += src[HW];
        om2 += src[2 * HW];
    }
    float mk = sigf(om2);
    float linx = -1.f + 2.f * xx / (WW - 1);
    float liny = -1.f + 2.f * yy / (HH - 1);
    float gx = (linx + om1 * (2.f / WW) + 1.f) * 0.5f * (WW - 1);
    float gy = (liny + om0 * (2.f / HH) + 1.f) * 0.5f * (HH - 1);
    float x0f = floorf(gx), y0f = floorf(gy);
    float wx = gx - x0f, wy = gy - y0f;
    int x0 = (int)x0f, y0 = (int)y0f;
    bool vx0 = (x0 >= 0 && x0 < WW), vx1 = (x0 + 1 >= 0 && x0 + 1 < WW);
    bool vy0 = (y0 >= 0 && y0 < HH), vy1 = (y0 + 1 >= 0 && y0 + 1 < HH);
    int cx0 = min(max(x0, 0), WW - 1), cx1 = min(max(x0 + 1, 0), WW - 1);
    int cy0 = min(max(y0, 0), HH - 1), cy1 = min(max(y0 + 1, 0), HH - 1);
    float4 w;
    w.x = (1.f - wx) * (1.f - wy) * mk * (vx0 && vy0 ? 1.f : 0.f);
    w.y = wx * (1.f - wy) * mk * (vx1 && vy0 ? 1.f : 0.f);
    w.z = (1.f - wx) * wy * mk * (vx0 && vy1 ? 1.f : 0.f);
    w.w = wx * wy * mk * (vx1 && vy1 ? 1.f : 0.f);
    int4 ix;
    ix.x = cy0 * WW + cx0;
    ix.y = cy0 * WW + cx1;
    ix.z = cy1 * WW + cx0;
    ix.w = cy1 * WW + cx1;
    g_spw[(size_t)b * HW + p] = w;
    g_spi[(size_t)b * HW + p] = ix;
}

// ---------------- K4: grid sample * mask (params precomputed, channel-split z=4) ----------------
__global__ void __launch_bounds__(256)
k_sample_t() {
    const int p = blockIdx.x * 256 + threadIdx.x;
    const int b = blockIdx.y;
    const int c0 = blockIdx.z * 16;

    float4 w = g_spw[(size_t)b * HW + p];
    int4 ix = g_spi[(size_t)b * HW + p];

    const float* im = g_h + ((size_t)b * CMID + c0) * HW;
    float* dst = g_xd + ((size_t)b * CS + c0) * HW + p;
#pragma unroll 4
    for (int c = 0; c < 16; c++) {
        const float* pl = im + (size_t)c * HW;
        float r = w.x * pl[ix.x] + w.y * pl[ix.y] + w.z * pl[ix.z] + w.w * pl[ix.w];
        dst[(size_t)c * HW] = r;
    }
}

// ---------------- K5: depthwise 3x3 pad1 on xd (tiled) ----------------
__global__ void __launch_bounds__(256)
k_dw3x3_t(const float* __restrict__ wdw) {
    __shared__ float tile[18][82];
    const int y0 = blockIdx.x * 16;
    const int bc = blockIdx.y;
    const int c = bc & 63;
    const int tid = threadIdx.x;
    const int r = tid >> 4;
    const int xg = (tid & 15) * 5;

    const float* im = g_xd + (size_t)bc * HW;
    for (int i = tid; i < 18 * 82; i += 256) {
        int rr = i / 82, col = i % 82;
        int gy = y0 - 1 + rr, gx = col - 1;
        float v = 0.f;
        if (gy >= 0 && gy < HH && gx >= 0 && gx < WW) v = im[gy * WW + gx];
        tile[rr][col] = v;
    }
    float w[9];
#pragma unroll
    for (int k = 0; k < 9; k++) w[k] = wdw[c * 9 + k];
    __syncthreads();

    float acc[5] = {0.f, 0.f, 0.f, 0.f, 0.f};
#pragma unroll
    for (int ky = 0; ky < 3; ky++) {
        float s[7];
#pragma unroll
        for (int j = 0; j < 7; j++) s[j] = tile[r + ky][xg + j];
#pragma unroll
        for (int i = 0; i < 5; i++)
#pragma unroll
            for (int kx = 0; kx < 3; kx++)
                acc[i] = fmaf(w[ky * 3 + kx], s[i + kx], acc[i]);
    }
    float* dst = g_t1 + (size_t)bc * HW + (y0 + r) * WW + xg;
#pragma unroll
    for (int i = 0; i < 5; i++) dst[i] = acc[i];
}

// ---------------- K6: pw 1x1 (64->64) + BN + SiLU via mma.sync bf16x3 ----------------
__global__ void __launch_bounds__(256, 1)
k_pw_mma(const float* __restrict__ bnp) {
    extern __shared__ char sm[];
    const int b = blockIdx.y;
    const int p0 = blockIdx.x * 128;
    const int tid = threadIdx.x;
    const int wid = tid >> 5;
    const int lane = tid & 31;
    const int g = lane >> 2, t = lane & 3;
    const int warp_m = wid >> 2;
    const int warp_n = wid & 3;

    float c[2][4][4];
#pragma unroll
    for (int mf = 0; mf < 2; mf++)
#pragma unroll
        for (int nf = 0; nf < 4; nf++)
#pragma unroll
            for (int i = 0; i < 4; i++) c[mf][nf][i] = 0.f;

#pragma unroll
    for (int i = 0; i < 8; i++) {
        int p = i * 256 + tid;
        int oc = p >> 5, j = p & 31;
        *(uint32_t*)(sm + PW_A_HI + oc * TSTRIDE + j * 4) = g_wpw_h[p];
        *(uint32_t*)(sm + PW_A_LO + oc * TSTRIDE + j * 4) = g_wpw_l[p];
    }
    const float* tb = g_t1 + (size_t)b * CS * HW + p0;
#pragma unroll
    for (int i = 0; i < 16; i++) {
        int p = i * 256 + tid;
        int px = p & 127, kp = p >> 7;
        const float* src = tb + (size_t)(2 * kp) * HW + px;
        uint32_t hi, lo;
        split2(src[0], src[HW], hi, lo);
        *(uint32_t*)(sm + PW_B_HI + px * TSTRIDE + kp * 4) = hi;
        *(uint32_t*)(sm + PW_B_LO + px * TSTRIDE + kp * 4) = lo;
    }
    __syncthreads();
#pragma unroll
    for (int ks = 0; ks < 4; ks++) {
        const int kk = ks * 16;
        uint32_t ahi[2][4], alo[2][4];
#pragma unroll
        for (int mf = 0; mf < 2; mf++) {
            int r0 = warp_m * 32 + mf * 16;
            const char* ph = sm + PW_A_HI + (r0 + g) * TSTRIDE + (kk + 2 * t) * 2;
            ahi[mf][0] = *(const uint32_t*)(ph);
            ahi[mf][1] = *(const uint32_t*)(ph + 8 * TSTRIDE);
            ahi[mf][2] = *(const uint32_t*)(ph + 16);
            ahi[mf][3] = *(const uint32_t*)(ph + 8 * TSTRIDE + 16);
            const char* pl = sm + PW_A_LO + (r0 + g) * TSTRIDE + (kk + 2 * t) * 2;
            alo[mf][0] = *(const uint32_t*)(pl);
            alo[mf][1] = *(const uint32_t*)(pl + 8 * TSTRIDE);
            alo[mf][2] = *(const uint32_t*)(pl + 16);
            alo[mf][3] = *(const uint32_t*)(pl + 8 * TSTRIDE + 16);
        }
        uint32_t bhi[4][2], blo[4][2];
#pragma unroll
        for (int nf = 0; nf < 4; nf++) {
            int n0 = warp_n * 32 + nf * 8;
            const char* ph = sm + PW_B_HI + (n0 + g) * TSTRIDE + (kk + 2 * t) * 2;
            bhi[nf][0] = *(const uint32_t*)(ph);
            bhi[nf][1] = *(const uint32_t*)(ph + 16);
            const char* pl = sm + PW_B_LO + (n0 + g) * TSTRIDE + (kk + 2 * t) * 2;
            blo[nf][0] = *(const uint32_t*)(pl);
            blo[nf][1] = *(const uint32_t*)(pl + 16);
        }
#pragma unroll
        for (int mf = 0; mf < 2; mf++)
#pragma unroll
            for (int nf = 0; nf < 4; nf++) {
                mma16816(c[mf][nf], ahi[mf], bhi[nf]);
                mma16816(c[mf][nf], ahi[mf], blo[nf]);
                mma16816(c[mf][nf], alo[mf], bhi[nf]);
            }
    }

#pragma unroll
    for (int mf = 0; mf < 2; mf++) {
        int ocA = warp_m * 32 + mf * 16 + g;
        int ocB = ocA + 8;
        float gA = bnp[ocA], bA = bnp[64 + ocA], mA = bnp[128 + ocA], vA = bnp[192 + ocA];
        float sA = gA * rsqrtf(vA + 1e-5f), shA = bA - mA * sA;
        float gB = bnp[ocB], bB = bnp[64 + ocB], mB = bnp[128 + ocB], vB = bnp[192 + ocB];
        float sB = gB * rsqrtf(vB + 1e-5f), shB = bB - mB * sB;
        float* dA = g_dcn + ((size_t)b * CS + ocA) * HW + p0 + warp_n * 32;
        float* dB = g_dcn + ((size_t)b * CS + ocB) * HW + p0 + warp_n * 32;
#pragma unroll
        for (int nf = 0; nf < 4; nf++) {
            int px = nf * 8 + 2 * t;
            *(float2*)(dA + px) = make_float2(siluf(c[mf][nf][0] * sA + shA),
                                              siluf(c[mf][nf][1] * sA + shA));
            *(float2*)(dB + px) = make_float2(siluf(c[mf][nf][2] * sB + shB),
                                              siluf(c[mf][nf][3] * sB + shB));
        }
    }
}

// ---------------- K7: fused d2 + d3 + asym1 + asym2 + ctx blend + star + chmean ----------------
__global__ void __launch_bounds__(256)
k_ctx_star(const float* __restrict__ wd2, const float* __restrict__ bnd2,
           const float* __restrict__ wd3, const float* __restrict__ bnd3,
           const float* __restrict__ wa1, const float* __restrict__ bna1,
           const float* __restrict__ wa2, const float* __restrict__ bna2,
           const float* __restrict__ cw, const float* __restrict__ bns) {
    __shared__ float hst[22][86];
    __shared__ float sa1[22][80];
    __shared__ float ssum[256];
    const int y0 = blockIdx.x * 16;
    const int bc = blockIdx.y;
    const int b = bc >> 6, c = bc & 63;
    const int tid = threadIdx.x;
    const int r = tid >> 4;
    const int xg = (tid & 15) * 5;

    const float* im = g_h + ((size_t)b * CMID + c) * HW;
    for (int i = tid; i < 22 * 86; i += 256) {
        int rr = i / 86, col = i % 86;
        int gy = y0 - 3 + rr, gx = col - 3;
        float v = 0.f;
        if (gy >= 0 && gy < HH && gx >= 0 && gx < WW) v = im[gy * WW + gx];
        hst[rr][col] = v;
    }
    float wa1r[7], wa2r[7], wd2r[9], wd3r[9];
#pragma unroll
    for (int k = 0; k < 7; k++) { wa1r[k] = wa1[c * 7 + k]; wa2r[k] = wa2[c * 7 + k]; }
#pragma unroll
    for (int k = 0; k < 9; k++) { wd2r[k] = wd2[c * 9 + k]; wd3r[k] = wd3[c * 9 + k]; }
    float sA1 = bna1[c] * rsqrtf(bna1[192 + c] + 1e-5f);
    float hA1 = bna1[64 + c] - bna1[128 + c] * sA1;
    float sA2 = bna2[c] * rsqrtf(bna2[192 + c] + 1e-5f);
    float hA2 = bna2[64 + c] - bna2[128 + c] * sA2;
    float sD2 = bnd2[c] * rsqrtf(bnd2[192 + c] + 1e-5f);
    float hD2 = bnd2[64 + c] - bnd2[128 + c] * sD2;
    float sD3 = bnd3[c] * rsqrtf(bnd3[192 + c] + 1e-5f);
    float hD3 = bnd3[64 + c] - bnd3[128 + c] * sD3;
    float sST = bns[c] * rsqrtf(bns[192 + c] + 1e-5f);
    float hST = bns[64 + c] - bns[128 + c] * sST;
    float e0 = __expf(cw[0]), e1 = __expf(cw[1]), e2 = __expf(cw[2]);
    float inv = 1.f / (e0 + e1 + e2);
    float cw0 = e0 * inv, cw1 = e1 * inv, cw2 = e2 * inv;
    __syncthreads();

    for (int i = tid; i < 22 * 80; i += 256) {
        int rr = i / 80, col = i % 80;
        int gy = y0 - 3 + rr;
        float v = 0.f;
        if (gy >= 0 && gy < HH) {
            float a = 0.f;
#pragma unroll
            for (int k = 0; k < 7; k++) a = fmaf(wa1r[k], hst[rr][col + k], a);
            v = siluf(a * sA1 + hA1);
        }
        sa1[rr][col] = v;
    }
    __syncthreads();

    const float* dcnp = g_dcn + (size_t)bc * HW;
    float* starp = g_star + (size_t)bc * HW;
    float lsum = 0.f;
#pragma unroll
    for (int i = 0; i < 5; i++) {
        int col = xg + i;
        float d2 = 0.f, d3 = 0.f;
#pragma unroll
        for (int ky = 0; ky < 3; ky++)
#pragma unroll
            for (int kx = 0; kx < 3; kx++) {
                d2 = fmaf(wd2r[ky * 3 + kx], hst[r + 3 + 2 * (ky - 1)][col + 3 + 2 * (kx - 1)], d2);
                d3 = fmaf(wd3r[ky * 3 + kx], hst[r + 3 + 3 * (ky - 1)][col + 3 + 3 * (kx - 1)], d3);
            }
        float a2 = 0.f;
#pragma unroll
        for (int ky = 0; ky < 7; ky++) a2 = fmaf(wa2r[ky], sa1[r + ky][col], a2);
        float ctx = cw0 * siluf(d2 * sD2 + hD2)
                  + cw1 * siluf(d3 * sD3 + hD3)
                  + cw2 * siluf(a2 * sA2 + hA2);
        int p = (y0 + r) * WW + col;
        float st = (dcnp[p] * ctx) * sST + hST;
        starp[p] = st;
        lsum += st;
    }
    ssum[tid] = lsum;
    __syncthreads();
    for (int o = 128; o > 0; o >>= 1) {
        if (tid < o) ssum[tid] += ssum[tid + o];
        __syncthreads();
    }
    if (tid == 0) atomicAdd(&g_chmean[bc], ssum[0]);
}

// ---------------- K8: ECA conv1d(k=5,pad=2) + sigmoid ----------------
__global__ void k_eca(const float* __restrict__ ew) {
    int b = blockIdx.x;
    int c = threadIdx.x;
    __shared__ float sm[CS];
    sm[c] = g_chmean[b * CS + c] * (1.f / (float)HW);
    __syncthreads();
    float s = 0.f;
#pragma unroll
    for (int k = 0; k < 5; k++) {
        int cc = c - 2 + k;
        if (cc >= 0 && cc < CS) s = fmaf(ew[k], sm[cc], s);
    }
    g_ych[b * CS + c] = sigf(s);
}

// ---------------- K9: spatial mean/max (channel-quad split) ----------------
__global__ void __launch_bounds__(256)
k_spstat() {
    __shared__ float ys[CS];
    __shared__ float smean[4][64];
    __shared__ float smax[4][64];
    const int b = blockIdx.y;
    const int px = threadIdx.x & 63;
    const int q = threadIdx.x >> 6;
    const int p = blockIdx.x * 64 + px;
    if (threadIdx.x < CS) ys[threadIdx.x] = g_ych[b * CS + threadIdx.x];
    __syncthreads();
    float s = 0.f, mx = -3.4e38f;
    const float* base = g_star + ((size_t)b * CS + q * 16) * HW + p;
#pragma unroll 4
    for (int c = 0; c < 16; c++) {
        float v = base[(size_t)c * HW] * ys[q * 16 + c];
        s += v;
        mx = fmaxf(mx, v);
    }
    smean[q][px] = s;
    smax[q][px] = mx;
    __syncthreads();
    if (q == 0) {
#pragma unroll
        for (int k = 1; k < 4; k++) {
            s += smean[k][px];
            mx = fmaxf(mx, smax[k][px]);
        }
        g_spmean[(size_t)b * HW + p] = s * (1.f / (float)CS);
        g_spmax[(size_t)b * HW + p] = mx;
    }
}

// ---------------- K10: spatial attention conv 7x7 (2->1) + sigmoid (tiled) ----------------
__global__ void __launch_bounds__(256)
k_satt_t(const float* __restrict__ sw) {
    __shared__ float m0t[22][86];
    __shared__ float m1t[22][86];
    const int y0 = blockIdx.x * 16;
    const int b = blockIdx.y;
    const int tid = threadIdx.x;
    const int r = tid >> 4;
    const int xg = (tid & 15) * 5;

    const float* m0 = g_spmean + (size_t)b * HW;
    const float* m1 = g_spmax + (size_t)b * HW;
    for (int i = tid; i < 22 * 86; i += 256) {
        int rr = i / 86, col = i % 86;
        int gy = y0 - 3 + rr, gx = col - 3;
        float v0 = 0.f, v1 = 0.f;
        if (gy >= 0 && gy < HH && gx >= 0 && gx < WW) {
            v0 = m0[gy * WW + gx];
            v1 = m1[gy * WW + gx];
        }
        m0t[rr][col] = v0;
        m1t[rr][col] = v1;
    }
    __syncthreads();
    float* dst = g_satt + (size_t)b * HW + (y0 + r) * WW + xg;
#pragma unroll
    for (int i = 0; i < 5; i++) {
        float s = 0.f;
#pragma unroll
        for (int ky = 0; ky < 7; ky++)
#pragma unroll
            for (int kx = 0; kx < 7; kx++) {
                s = fmaf(sw[ky * 7 + kx], m0t[r + ky][xg + i + kx], s);
                s = fmaf(sw[49 + ky * 7 + kx], m1t[r + ky][xg + i + kx], s);
            }
        dst[i] = sigf(s);
    }
}

// ---------------- K11: expand 1x1 (128->256) + BN + SiLU + residual via mma.sync ----------------
__global__ void __launch_bounds__(256, 1)
k_expand_mma(const float* __restrict__ x, const float* __restrict__ bne,
             const float* __restrict__ bw, float* __restrict__ out) {
    extern __shared__ char sm[];
    const int b = blockIdx.y;
    const int p0 = blockIdx.x * 128;
    const int oc0 = blockIdx.z * 128;
    const int tid = threadIdx.x;
    const int wid = tid >> 5;
    const int lane = tid & 31;
    const int g = lane >> 2, t = lane & 3;
    const int warp_m = wid >> 1;
    const int warp_n = wid & 1;

    const float alpha = 1.f / (1.f + __expf(-bw[0]));
    const float oma = 1.f - alpha;

    float c[2][8][4];
#pragma unroll
    for (int mf = 0; mf < 2; mf++)
#pragma unroll
        for (int nf = 0; nf < 8; nf++)
#pragma unroll
            for (int i = 0; i < 4; i++) c[mf][nf][i] = 0.f;

    for (int kc = 0; kc < 2; kc++) {
#pragma unroll
        for (int i = 0; i < 16; i++) {
            int p = i * 256 + tid;
            int oc = p >> 5, j = p & 31;
            int q = (oc0 + oc) * 64 + kc * 32 + j;
            *(uint32_t*)(sm + OFF_A_HI + oc * TSTRIDE + j * 4) = g_wexp_h[q];
            *(uint32_t*)(sm + OFF_A_LO + oc * TSTRIDE + j * 4) = g_wexp_l[q];
        }
#pragma unroll
        for (int i = 0; i < 16; i++) {
            int p = i * 256 + tid;
            int px = p & 127, kp = p >> 7;
            int ch = kc * 32 + kp;
            float v0 = g_star[((size_t)b * CS + ch) * HW + p0 + px]
                     * g_ych[b * CS + ch]
                     * g_satt[(size_t)b * HW + p0 + px] * alpha;
            float v1 = g_h[((size_t)b * CMID + CS + ch) * HW + p0 + px] * oma;
            uint32_t hi, lo;
            split2(v0, v1, hi, lo);
            *(uint32_t*)(sm + OFF_B_HI + px * TSTRIDE + kp * 4) = hi;
            *(uint32_t*)(sm + OFF_B_LO + px * TSTRIDE + kp * 4) = lo;
        }
        __syncthreads();
#pragma unroll
        for (int ks = 0; ks < 4; ks++) {
            const int kk = ks * 16;
            uint32_t ahi[2][4], alo[2][4];
#pragma unroll
            for (int mf = 0; mf < 2; mf++) {
                int r0 = warp_m * 32 + mf * 16;
                const char* ph = sm + OFF_A_HI + (r0 + g) * TSTRIDE + (kk + 2 * t) * 2;
                ahi[mf][0] = *(const uint32_t*)(ph);
                ahi[mf][1] = *(const uint32_t*)(ph + 8 * TSTRIDE);
                ahi[mf][2] = *(const uint32_t*)(ph + 16);
                ahi[mf][3] = *(const uint32_t*)(ph + 8 * TSTRIDE + 16);
                const char* pl = sm + OFF_A_LO + (r0 + g) * TSTRIDE + (kk + 2 * t) * 2;
                alo[mf][0] = *(const uint32_t*)(pl);
                alo[mf][1] = *(const uint32_t*)(pl + 8 * TSTRIDE);
                alo[mf][2] = *(const uint32_t*)(pl + 16);
                alo[mf][3] = *(const uint32_t*)(pl + 8 * TSTRIDE + 16);
            }
            uint32_t bhi[8][2], blo[8][2];
#pragma unroll
            for (int nf = 0; nf < 8; nf++) {
                int n0 = warp_n * 64 + nf * 8;
                const char* ph = sm + OFF_B_HI + (n0 + g) * TSTRIDE + (kk + 2 * t) * 2;
                bhi[nf][0] = *(const uint32_t*)(ph);
                bhi[nf][1] = *(const uint32_t*)(ph + 16);
                const char* pl = sm + OFF_B_LO + (n0 + g) * TSTRIDE + (kk + 2 * t) * 2;
                blo[nf][0] = *(const uint32_t*)(pl);
                blo[nf][1] = *(const uint32_t*)(pl + 16);
            }
#pragma unroll
            for (int mf = 0; mf < 2; mf++)
#pragma unroll
                for (int nf = 0; nf < 8; nf++) {
                    mma16816(c[mf][nf], ahi[mf], bhi[nf]);
                    mma16816(c[mf][nf], ahi[mf], blo[nf]);
                    mma16816(c[mf][nf], alo[mf], bhi[nf]);
                }
        }
        __syncthreads();
    }

#pragma unroll
    for (int mf = 0; mf < 2; mf++) {
        int ocA = oc0 + warp_m * 32 + mf * 16 + g;
        int ocB = ocA + 8;
        float gA = bne[ocA], bA = bne[256 + ocA], mA = bne[512 + ocA], vA = bne[768 + ocA];
        float sA = gA * rsqrtf(vA + 1e-5f), shA = bA - mA * sA;
        float gB = bne[ocB], bB = bne[256 + ocB], mB = bne[512 + ocB], vB = bne[768 + ocB];
        float sB = gB * rsqrtf(vB + 1e-5f), shB = bB - mB * sB;
        float* dA = out + ((size_t)b * C1 + ocA) * HW + p0 + warp_n * 64;
        float* dB = out + ((size_t)b * C1 + ocB) * HW + p0 + warp_n * 64;
        const float* rA = x + ((size_t)b * C1 + ocA) * HW + p0 + warp_n * 64;
        const float* rB = x + ((size_t)b * C1 + ocB) * HW + p0 + warp_n * 64;
#pragma unroll
        for (int nf = 0; nf < 8; nf++) {
            int px = nf * 8 + 2 * t;
            float2 resA = *(const float2*)(rA + px);
            float2 resB = *(const float2*)(rB + px);
            *(float2*)(dA + px) = make_float2(siluf(c[mf][nf][0] * sA + shA) + resA.x,
                                              siluf(c[mf][nf][1] * sA + shA) + resA.y);
            *(float2*)(dB + px) = make_float2(siluf(c[mf][nf][2] * sB + shB) + resB.x,
                                              siluf(c[mf][nf][3] * sB + shB) + resB.y);
        }
    }
}

// ---------------- launch ----------------
extern "C" void kernel_launch(void* const* d_in, const int* in_sizes, int n_in,
                              void* d_out, int out_size) {
    const float* x          = (const float*)d_in[0];
    const float* w_reduce   = (const float*)d_in[1];
    const float* bn_reduce  = (const float*)d_in[2];
    const float* dcn_off_w  = (const float*)d_in[3];
    const float* dcn_off_b  = (const float*)d_in[4];
    const float* dcn_dw_w   = (const float*)d_in[5];
    const float* dcn_pw_w   = (const float*)d_in[6];
    const float* bn_dcn     = (const float*)d_in[7];
    const float* w_d2       = (const float*)d_in[8];
    const float* bn_d2      = (const float*)d_in[9];
    const float* w_d3       = (const float*)d_in[10];
    const float* bn_d3      = (const float*)d_in[11];
    const float* w_asym1    = (const float*)d_in[12];
    const float* bn_asym1   = (const float*)d_in[13];
    const float* w_asym2    = (const float*)d_in[14];
    const float* bn_asym2   = (const float*)d_in[15];
    const float* ctx_weight = (const float*)d_in[16];
    const float* bn_star    = (const float*)d_in[17];
    const float* eca_w      = (const float*)d_in[18];
    const float* sp_w       = (const float*)d_in[19];
    const float* blend_w    = (const float*)d_in[20];
    const float* w_expand   = (const float*)d_in[21];
    const float* bn_expand  = (const float*)d_in[22];
    float* out = (float*)d_out;

    static bool attr_done = false;
    if (!attr_done) {
        cudaFuncSetAttribute(k_reduce_mma, cudaFuncAttributeMaxDynamicSharedMemorySize, GEMM_SMEM);
        cudaFuncSetAttribute(k_expand_mma, cudaFuncAttributeMaxDynamicSharedMemorySize, GEMM_SMEM);
        cudaFuncSetAttribute(k_pw_mma, cudaFuncAttributeMaxDynamicSharedMemorySize, PW_SMEM);
        attr_done = true;
    }

    k_zero<<<4, 256>>>();
    k_prepw<<<136, 256>>>(w_reduce, w_expand, dcn_pw_w);
    k_reduce_mma<<<dim3(HW / 128, BB), 256, GEMM_SMEM>>>(x, bn_reduce);
    k_offconv_t<<<dim3(NGRP, 5, BB), 256>>>(dcn_off_w);
    k_omsum<<<dim3(HW / 256, BB), 256>>>(dcn_off_b);
    k_sample_t<<<dim3(HW / 256, BB, 4), 256>>>();
    k_dw3x3_t<<<dim3(5, BB * CS), 256>>>(dcn_dw_w);
    k_pw_mma<<<dim3(HW / 128, BB), 256, PW_SMEM>>>(bn_dcn);
    k_ctx_star<<<dim3(5, BB * CS), 256>>>(w_d2, bn_d2, w_d3, bn_d3,
                                          w_asym1, bn_asym1, w_asym2, bn_asym2,
                                          ctx_weight, bn_star);
    k_eca<<<BB, CS>>>(eca_w);
    k_spstat<<<dim3(HW / 64, BB), 256>>>();
    k_satt_t<<<dim3(5, BB), 256>>>(sp_w);
    k_expand_mma<<<dim3(HW / 128, BB, 2), 256, GEMM_SMEM>>>(x, bn_expand, blend_w, out);
}

// round 12
// speedup vs baseline: 1.5723x; 1.1218x over previous
#include <cuda_runtime.h>
#include <cuda_bf16.h>
#include <cstdint>

#define BB 16
#define C1 256
#define CMID 128
#define CS 64
#define HH 80
#define WW 80
#define HW 6400
#define NGRP 32

// ---------------- scratch (device globals; no allocations) ----------------
__device__ float g_h[(size_t)BB*CMID*HW];     // reduce output (hs ch 0..63, hb 64..127)
__device__ float g_omp[(size_t)NGRP*BB*3*HW]; // offset conv partials (32 channel groups)
__device__ float4 g_spw[(size_t)BB*HW];       // bilinear weights (mask folded)
__device__ int4   g_spi[(size_t)BB*HW];       // gather indices (clamped)
__device__ float g_xd[(size_t)BB*CS*HW];      // grid-sampled * mask
__device__ float g_t1[(size_t)BB*CS*HW];      // dcn depthwise out
__device__ float g_dcn[(size_t)BB*CS*HW];     // dcn branch
__device__ float g_star[(size_t)BB*CS*HW];    // star0 = bn_star(dcn*ctx)
__device__ float g_chmean[BB*CS];             // raw channel sums (atomic)
__device__ float g_ych[BB*CS];
__device__ float g_spmean[(size_t)BB*HW];
__device__ float g_spmax[(size_t)BB*HW];
__device__ float g_satt[(size_t)BB*HW];
// pre-split bf16 hi/lo weights (k-pair packed)
__device__ uint32_t g_wred_h[128*128], g_wred_l[128*128];
__device__ uint32_t g_wexp_h[256*64],  g_wexp_l[256*64];
__device__ uint32_t g_wpw_h[64*32],    g_wpw_l[64*32];

__device__ __forceinline__ float siluf(float v) { return v / (1.f + __expf(-v)); }
__device__ __forceinline__ float sigf(float v)  { return 1.f / (1.f + __expf(-v)); }

// ---------------- mma.sync helpers ----------------
__device__ __forceinline__ void mma16816(float* c, const uint32_t* a, const uint32_t* b) {
    asm volatile(
        "mma.sync.aligned.m16n8k16.row.col.f32.bf16.bf16.f32 "
        "{%0,%1,%2,%3}, {%4,%5,%6,%7}, {%8,%9}, {%0,%1,%2,%3};"
        : "+f"(c[0]), "+f"(c[1]), "+f"(c[2]), "+f"(c[3])
        : "r"(a[0]), "r"(a[1]), "r"(a[2]), "r"(a[3]), "r"(b[0]), "r"(b[1]));
}

__device__ __forceinline__ void split2(float v0, float v1, uint32_t& hi, uint32_t& lo) {
    __nv_bfloat16 h0 = __float2bfloat16(v0);
    __nv_bfloat16 h1 = __float2bfloat16(v1);
    __nv_bfloat16 l0 = __float2bfloat16(v0 - __bfloat162float(h0));
    __nv_bfloat16 l1 = __float2bfloat16(v1 - __bfloat162float(h1));
    __nv_bfloat162 th(h0, h1), tl(l0, l1);
    hi = *(uint32_t*)&th;
    lo = *(uint32_t*)&tl;
}

#define TSTRIDE 144
#define TILE_BYTES (128 * TSTRIDE)           // 18432
#define OFF_A_HI 0
#define OFF_A_LO TILE_BYTES
#define OFF_B_HI (2 * TILE_BYTES)
#define OFF_B_LO (3 * TILE_BYTES)
#define GEMM_SMEM (4 * TILE_BYTES)           // 73728

#define PW_A_HI 0
#define PW_A_LO (64 * TSTRIDE)
#define PW_B_HI (2 * 64 * TSTRIDE)
#define PW_B_LO (PW_B_HI + 128 * TSTRIDE)
#define PW_SMEM (PW_B_LO + 128 * TSTRIDE)    // 55296

// ---------------- K0: zero accumulators + pre-split GEMM weights ----------------
__global__ void k_prepw(const float* __restrict__ wred, const float* __restrict__ wexp,
                        const float* __restrict__ wpw) {
    int idx = blockIdx.x * 256 + threadIdx.x;   // 0..34815
    if (idx < 1024) g_chmean[idx] = 0.f;
    if (idx < 16384) {
        int oc = idx >> 7, j = idx & 127;
        split2(wred[oc * 256 + 2 * j], wred[oc * 256 + 2 * j + 1],
               g_wred_h[idx], g_wred_l[idx]);
    } else if (idx < 32768) {
        int q = idx - 16384;
        int oc = q >> 6, j = q & 63;
        split2(wexp[oc * 128 + 2 * j], wexp[oc * 128 + 2 * j + 1],
               g_wexp_h[q], g_wexp_l[q]);
    } else {
        int q = idx - 32768;
        int oc = q >> 5, j = q & 31;
        split2(wpw[oc * 64 + 2 * j], wpw[oc * 64 + 2 * j + 1],
               g_wpw_h[q], g_wpw_l[q]);
    }
}

// ---------------- K1: reduce 1x1 (256->128) + BN + SiLU via mma.sync bf16x3 ----------------
__global__ void __launch_bounds__(256, 2)
k_reduce_mma(const float* __restrict__ x, const float* __restrict__ bnr) {
    extern __shared__ char sm[];
    const int b = blockIdx.y;
    const int p0 = blockIdx.x * 128;
    const int tid = threadIdx.x;
    const int wid = tid >> 5;
    const int lane = tid & 31;
    const int g = lane >> 2, t = lane & 3;
    const int warp_m = wid >> 1;
    const int warp_n = wid & 1;

    float c[2][8][4];
#pragma unroll
    for (int mf = 0; mf < 2; mf++)
#pragma unroll
        for (int nf = 0; nf < 8; nf++)
#pragma unroll
            for (int i = 0; i < 4; i++) c[mf][nf][i] = 0.f;

    const float* xb = x + (size_t)b * C1 * HW + p0;

    for (int kc = 0; kc < 4; kc++) {
#pragma unroll
        for (int i = 0; i < 16; i++) {
            int p = i * 256 + tid;
            int oc = p >> 5, j = p & 31;
            int q = oc * 128 + kc * 32 + j;
            *(uint32_t*)(sm + OFF_A_HI + oc * TSTRIDE + j * 4) = g_wred_h[q];
            *(uint32_t*)(sm + OFF_A_LO + oc * TSTRIDE + j * 4) = g_wred_l[q];
        }
#pragma unroll
        for (int i = 0; i < 16; i++) {
            int p = i * 256 + tid;
            int px = p & 127, kp = p >> 7;
            const float* src = xb + (size_t)(kc * 64 + 2 * kp) * HW + px;
            uint32_t hi, lo;
            split2(src[0], src[HW], hi, lo);
            *(uint32_t*)(sm + OFF_B_HI + px * TSTRIDE + kp * 4) = hi;
            *(uint32_t*)(sm + OFF_B_LO + px * TSTRIDE + kp * 4) = lo;
        }
        __syncthreads();
#pragma unroll
        for (int ks = 0; ks < 4; ks++) {
            const int kk = ks * 16;
            uint32_t ahi[2][4], alo[2][4];
#pragma unroll
            for (int mf = 0; mf < 2; mf++) {
                int r0 = warp_m * 32 + mf * 16;
                const char* ph = sm + OFF_A_HI + (r0 + g) * TSTRIDE + (kk + 2 * t) * 2;
                ahi[mf][0] = *(const uint32_t*)(ph);
                ahi[mf][1] = *(const uint32_t*)(ph + 8 * TSTRIDE);
                ahi[mf][2] = *(const uint32_t*)(ph + 16);
                ahi[mf][3] = *(const uint32_t*)(ph + 8 * TSTRIDE + 16);
                const char* pl = sm + OFF_A_LO + (r0 + g) * TSTRIDE + (kk + 2 * t) * 2;
                alo[mf][0] = *(const uint32_t*)(pl);
                alo[mf][1] = *(const uint32_t*)(pl + 8 * TSTRIDE);
                alo[mf][2] = *(const uint32_t*)(pl + 16);
                alo[mf][3] = *(const uint32_t*)(pl + 8 * TSTRIDE + 16);
            }
            uint32_t bhi[8][2], blo[8][2];
#pragma unroll
            for (int nf = 0; nf < 8; nf++) {
                int n0 = warp_n * 64 + nf * 8;
                const char* ph = sm + OFF_B_HI + (n0 + g) * TSTRIDE + (kk + 2 * t) * 2;
                bhi[nf][0] = *(const uint32_t*)(ph);
                bhi[nf][1] = *(const uint32_t*)(ph + 16);
                const char* pl = sm + OFF_B_LO + (n0 + g) * TSTRIDE + (kk + 2 * t) * 2;
                blo[nf][0] = *(const uint32_t*)(pl);
                blo[nf][1] = *(const uint32_t*)(pl + 16);
            }
#pragma unroll
            for (int mf = 0; mf < 2; mf++)
#pragma unroll
                for (int nf = 0; nf < 8; nf++) {
                    mma16816(c[mf][nf], ahi[mf], bhi[nf]);
                    mma16816(c[mf][nf], ahi[mf], blo[nf]);
                    mma16816(c[mf][nf], alo[mf], bhi[nf]);
                }
        }
        __syncthreads();
    }

#pragma unroll
    for (int mf = 0; mf < 2; mf++) {
        int ocA = warp_m * 32 + mf * 16 + g;
        int ocB = ocA + 8;
        float gA = bnr[ocA], bA = bnr[128 + ocA], mA = bnr[256 + ocA], vA = bnr[384 + ocA];
        float sA = gA * rsqrtf(vA + 1e-5f), shA = bA - mA * sA;
        float gB = bnr[ocB], bB = bnr[128 + ocB], mB = bnr[256 + ocB], vB = bnr[384 + ocB];
        float sB = gB * rsqrtf(vB + 1e-5f), shB = bB - mB * sB;
        float* dA = g_h + ((size_t)b * CMID + ocA) * HW + p0 + warp_n * 64;
        float* dB = g_h + ((size_t)b * CMID + ocB) * HW + p0 + warp_n * 64;
#pragma unroll
        for (int nf = 0; nf < 8; nf++) {
            int px = nf * 8 + 2 * t;
            *(float2*)(dA + px) = make_float2(siluf(c[mf][nf][0] * sA + shA),
                                              siluf(c[mf][nf][1] * sA + shA));
            *(float2*)(dB + px) = make_float2(siluf(c[mf][nf][2] * sB + shB),
                                              siluf(c[mf][nf][3] * sB + shB));
        }
    }
}

// ---------------- K2: offset conv 3x3 (2-ch group partials, 32 groups) ----------------
__global__ void __launch_bounds__(256)
k_offconv_t(const float* __restrict__ wo) {
    __shared__ float tile[18][82];
    __shared__ float sw[3][2][9];
    const int grp = blockIdx.x;
    const int y0 = blockIdx.y * 16;
    const int b = blockIdx.z;
    const int tid = threadIdx.x;
    const int r = tid >> 4;
    const int xg = (tid & 15) * 5;

    if (tid < 3 * 2 * 9) {
        int o = tid / 18, rest = tid % 18;
        int cc = rest / 9, k = rest % 9;
        sw[o][cc][k] = wo[o * 576 + (grp * 2 + cc) * 9 + k];
    }

    float acc[3][5];
#pragma unroll
    for (int o = 0; o < 3; o++)
#pragma unroll
        for (int i = 0; i < 5; i++) acc[o][i] = 0.f;

    __syncthreads();
    for (int cc = 0; cc < 2; cc++) {
        const float* im = g_h + ((size_t)b * CMID + grp * 2 + cc) * HW;
        for (int i = tid; i < 18 * 82; i += 256) {
            int rr = i / 82, col = i % 82;
            int gy = y0 - 1 + rr, gx = col - 1;
            float v = 0.f;
            if (gy >= 0 && gy < HH && gx >= 0 && gx < WW) v = im[gy * WW + gx];
            tile[rr][col] = v;
        }
        __syncthreads();
#pragma unroll
        for (int ky = 0; ky < 3; ky++) {
            float s[7];
#pragma unroll
            for (int j = 0; j < 7; j++) s[j] = tile[r + ky][xg + j];
#pragma unroll
            for (int o = 0; o < 3; o++) {
                float w0 = sw[o][cc][ky * 3 + 0];
                float w1 = sw[o][cc][ky * 3 + 1];
                float w2 = sw[o][cc][ky * 3 + 2];
#pragma unroll
                for (int i = 0; i < 5; i++) {
                    acc[o][i] = fmaf(w0, s[i], acc[o][i]);
                    acc[o][i] = fmaf(w1, s[i + 1], acc[o][i]);
                    acc[o][i] = fmaf(w2, s[i + 2], acc[o][i]);
                }
            }
        }
        __syncthreads();
    }
    float* dst = g_omp + ((size_t)grp * BB + b) * 3 * HW;
#pragma unroll
    for (int o = 0; o < 3; o++)
#pragma unroll
        for (int i = 0; i < 5; i++)
            dst[o * HW + (y0 + r) * WW + xg + i] = acc[o][i];
}

// ---------------- K3: sum offset partials + bake sampling params ----------------
__global__ void __launch_bounds__(256)
k_omsum(const float* __restrict__ bo) {
    const int p = blockIdx.x * 256 + threadIdx.x;
    const int b = blockIdx.y;
    const int xx = p % WW, yy = p / WW;

    float om0 = bo[0], om1 = bo[1], om2 = bo[2];
#pragma unroll 8
    for (int grp = 0; grp < NGRP; grp++) {
        const float* src = g_omp + ((size_t)grp * BB + b) * 3 * HW + p;
        om0 += src[0];
        om1 += src[HW];
        om2 += src[2 * HW];
    }
    float mk = sigf(om2);
    float linx = -1.f + 2.f * xx / (WW - 1);
    float liny = -1.f + 2.f * yy / (HH - 1);
    float gx = (linx + om1 * (2.f / WW) + 1.f) * 0.5f * (WW - 1);
    float gy = (liny + om0 * (2.f / HH) + 1.f) * 0.5f * (HH - 1);
    float x0f = floorf(gx), y0f = floorf(gy);
    float wx = gx - x0f, wy = gy - y0f;
    int x0 = (int)x0f, y0 = (int)y0f;
    bool vx0 = (x0 >= 0 && x0 < WW), vx1 = (x0 + 1 >= 0 && x0 + 1 < WW);
    bool vy0 = (y0 >= 0 && y0 < HH), vy1 = (y0 + 1 >= 0 && y0 + 1 < HH);
    int cx0 = min(max(x0, 0), WW - 1), cx1 = min(max(x0 + 1, 0), WW - 1);
    int cy0 = min(max(y0, 0), HH - 1), cy1 = min(max(y0 + 1, 0), HH - 1);
    float4 w;
    w.x = (1.f - wx) * (1.f - wy) * mk * (vx0 && vy0 ? 1.f : 0.f);
    w.y = wx * (1.f - wy) * mk * (vx1 && vy0 ? 1.f : 0.f);
    w.z = (1.f - wx) * wy * mk * (vx0 && vy1 ? 1.f : 0.f);
    w.w = wx * wy * mk * (vx1 && vy1 ? 1.f : 0.f);
    int4 ix;
    ix.x = cy0 * WW + cx0;
    ix.y = cy0 * WW + cx1;
    ix.z = cy1 * WW + cx0;
    ix.w = cy1 * WW + cx1;
    g_spw[(size_t)b * HW + p] = w;
    g_spi[(size_t)b * HW + p] = ix;
}

// ---------------- K4: grid sample * mask (params precomputed, channel-split z=4) ----------------
__global__ void __launch_bounds__(256)
k_sample_t() {
    const int p = blockIdx.x * 256 + threadIdx.x;
    const int b = blockIdx.y;
    const int c0 = blockIdx.z * 16;

    float4 w = g_spw[(size_t)b * HW + p];
    int4 ix = g_spi[(size_t)b * HW + p];

    const float* im = g_h + ((size_t)b * CMID + c0) * HW;
    float* dst = g_xd + ((size_t)b * CS + c0) * HW + p;
#pragma unroll 4
    for (int c = 0; c < 16; c++) {
        const float* pl = im + (size_t)c * HW;
        float r = w.x * pl[ix.x] + w.y * pl[ix.y] + w.z * pl[ix.z] + w.w * pl[ix.w];
        dst[(size_t)c * HW] = r;
    }
}

// ---------------- K5: depthwise 3x3 pad1 on xd (tiled) ----------------
__global__ void __launch_bounds__(256)
k_dw3x3_t(const float* __restrict__ wdw) {
    __shared__ float tile[18][82];
    const int y0 = blockIdx.x * 16;
    const int bc = blockIdx.y;
    const int c = bc & 63;
    const int tid = threadIdx.x;
    const int r = tid >> 4;
    const int xg = (tid & 15) * 5;

    const float* im = g_xd + (size_t)bc * HW;
    for (int i = tid; i < 18 * 82; i += 256) {
        int rr = i / 82, col = i % 82;
        int gy = y0 - 1 + rr, gx = col - 1;
        float v = 0.f;
        if (gy >= 0 && gy < HH && gx >= 0 && gx < WW) v = im[gy * WW + gx];
        tile[rr][col] = v;
    }
    float w[9];
#pragma unroll
    for (int k = 0; k < 9; k++) w[k] = wdw[c * 9 + k];
    __syncthreads();

    float acc[5] = {0.f, 0.f, 0.f, 0.f, 0.f};
#pragma unroll
    for (int ky = 0; ky < 3; ky++) {
        float s[7];
#pragma unroll
        for (int j = 0; j < 7; j++) s[j] = tile[r + ky][xg + j];
#pragma unroll
        for (int i = 0; i < 5; i++)
#pragma unroll
            for (int kx = 0; kx < 3; kx++)
                acc[i] = fmaf(w[ky * 3 + kx], s[i + kx], acc[i]);
    }
    float* dst = g_t1 + (size_t)bc * HW + (y0 + r) * WW + xg;
#pragma unroll
    for (int i = 0; i < 5; i++) dst[i] = acc[i];
}

// ---------------- K6: pw 1x1 (64->64) + BN + SiLU via mma.sync bf16x3 ----------------
__global__ void __launch_bounds__(256, 2)
k_pw_mma(const float* __restrict__ bnp) {
    extern __shared__ char sm[];
    const int b = blockIdx.y;
    const int p0 = blockIdx.x * 128;
    const int tid = threadIdx.x;
    const int wid = tid >> 5;
    const int lane = tid & 31;
    const int g = lane >> 2, t = lane & 3;
    const int warp_m = wid >> 2;
    const int warp_n = wid & 3;

    float c[2][4][4];
#pragma unroll
    for (int mf = 0; mf < 2; mf++)
#pragma unroll
        for (int nf = 0; nf < 4; nf++)
#pragma unroll
            for (int i = 0; i < 4; i++) c[mf][nf][i] = 0.f;

#pragma unroll
    for (int i = 0; i < 8; i++) {
        int p = i * 256 + tid;
        int oc = p >> 5, j = p & 31;
        *(uint32_t*)(sm + PW_A_HI + oc * TSTRIDE + j * 4) = g_wpw_h[p];
        *(uint32_t*)(sm + PW_A_LO + oc * TSTRIDE + j * 4) = g_wpw_l[p];
    }
    const float* tb = g_t1 + (size_t)b * CS * HW + p0;
#pragma unroll
    for (int i = 0; i < 16; i++) {
        int p = i * 256 + tid;
        int px = p & 127, kp = p >> 7;
        const float* src = tb + (size_t)(2 * kp) * HW + px;
        uint32_t hi, lo;
        split2(src[0], src[HW], hi, lo);
        *(uint32_t*)(sm + PW_B_HI + px * TSTRIDE + kp * 4) = hi;
        *(uint32_t*)(sm + PW_B_LO + px * TSTRIDE + kp * 4) = lo;
    }
    __syncthreads();
#pragma unroll
    for (int ks = 0; ks < 4; ks++) {
        const int kk = ks * 16;
        uint32_t ahi[2][4], alo[2][4];
#pragma unroll
        for (int mf = 0; mf < 2; mf++) {
            int r0 = warp_m * 32 + mf * 16;
            const char* ph = sm + PW_A_HI + (r0 + g) * TSTRIDE + (kk + 2 * t) * 2;
            ahi[mf][0] = *(const uint32_t*)(ph);
            ahi[mf][1] = *(const uint32_t*)(ph + 8 * TSTRIDE);
            ahi[mf][2] = *(const uint32_t*)(ph + 16);
            ahi[mf][3] = *(const uint32_t*)(ph + 8 * TSTRIDE + 16);
            const char* pl = sm + PW_A_LO + (r0 + g) * TSTRIDE + (kk + 2 * t) * 2;
            alo[mf][0] = *(const uint32_t*)(pl);
            alo[mf][1] = *(const uint32_t*)(pl + 8 * TSTRIDE);
            alo[mf][2] = *(const uint32_t*)(pl + 16);
            alo[mf][3] = *(const uint32_t*)(pl + 8 * TSTRIDE + 16);
        }
        uint32_t bhi[4][2], blo[4][2];
#pragma unroll
        for (int nf = 0; nf < 4; nf++) {
            int n0 = warp_n * 32 + nf * 8;
            const char* ph = sm + PW_B_HI + (n0 + g) * TSTRIDE + (kk + 2 * t) * 2;
            bhi[nf][0] = *(const uint32_t*)(ph);
            bhi[nf][1] = *(const uint32_t*)(ph + 16);
            const char* pl = sm + PW_B_LO + (n0 + g) * TSTRIDE + (kk + 2 * t) * 2;
            blo[nf][0] = *(const uint32_t*)(pl);
            blo[nf][1] = *(const uint32_t*)(pl + 16);
        }
#pragma unroll
        for (int mf = 0; mf < 2; mf++)
#pragma unroll
            for (int nf = 0; nf < 4; nf++) {
                mma16816(c[mf][nf], ahi[mf], bhi[nf]);
                mma16816(c[mf][nf], ahi[mf], blo[nf]);
                mma16816(c[mf][nf], alo[mf], bhi[nf]);
            }
    }

#pragma unroll
    for (int mf = 0; mf < 2; mf++) {
        int ocA = warp_m * 32 + mf * 16 + g;
        int ocB = ocA + 8;
        float gA = bnp[ocA], bA = bnp[64 + ocA], mA = bnp[128 + ocA], vA = bnp[192 + ocA];
        float sA = gA * rsqrtf(vA + 1e-5f), shA = bA - mA * sA;
        float gB = bnp[ocB], bB = bnp[64 + ocB], mB = bnp[128 + ocB], vB = bnp[192 + ocB];
        float sB = gB * rsqrtf(vB + 1e-5f), shB = bB - mB * sB;
        float* dA = g_dcn + ((size_t)b * CS + ocA) * HW + p0 + warp_n * 32;
        float* dB = g_dcn + ((size_t)b * CS + ocB) * HW + p0 + warp_n * 32;
#pragma unroll
        for (int nf = 0; nf < 4; nf++) {
            int px = nf * 8 + 2 * t;
            *(float2*)(dA + px) = make_float2(siluf(c[mf][nf][0] * sA + shA),
                                              siluf(c[mf][nf][1] * sA + shA));
            *(float2*)(dB + px) = make_float2(siluf(c[mf][nf][2] * sB + shB),
                                              siluf(c[mf][nf][3] * sB + shB));
        }
    }
}

// ---------------- K7: fused d2 + d3 + asym1 + asym2 + ctx blend + star + chmean ----------------
__global__ void __launch_bounds__(256)
k_ctx_star(const float* __restrict__ wd2, const float* __restrict__ bnd2,
           const float* __restrict__ wd3, const float* __restrict__ bnd3,
           const float* __restrict__ wa1, const float* __restrict__ bna1,
           const float* __restrict__ wa2, const float* __restrict__ bna2,
           const float* __restrict__ cw, const float* __restrict__ bns) {
    __shared__ float hst[22][86];
    __shared__ float sa1[22][80];
    __shared__ float ssum[256];
    const int y0 = blockIdx.x * 16;
    const int bc = blockIdx.y;
    const int b = bc >> 6, c = bc & 63;
    const int tid = threadIdx.x;
    const int r = tid >> 4;
    const int xg = (tid & 15) * 5;

    const float* im = g_h + ((size_t)b * CMID + c) * HW;
    for (int i = tid; i < 22 * 86; i += 256) {
        int rr = i / 86, col = i % 86;
        int gy = y0 - 3 + rr, gx = col - 3;
        float v = 0.f;
        if (gy >= 0 && gy < HH && gx >= 0 && gx < WW) v = im[gy * WW + gx];
        hst[rr][col] = v;
    }
    float wa1r[7], wa2r[7], wd2r[9], wd3r[9];
#pragma unroll
    for (int k = 0; k < 7; k++) { wa1r[k] = wa1[c * 7 + k]; wa2r[k] = wa2[c * 7 + k]; }
#pragma unroll
    for (int k = 0; k < 9; k++) { wd2r[k] = wd2[c * 9 + k]; wd3r[k] = wd3[c * 9 + k]; }
    float sA1 = bna1[c] * rsqrtf(bna1[192 + c] + 1e-5f);
    float hA1 = bna1[64 + c] - bna1[128 + c] * sA1;
    float sA2 = bna2[c] * rsqrtf(bna2[192 + c] + 1e-5f);
    float hA2 = bna2[64 + c] - bna2[128 + c] * sA2;
    float sD2 = bnd2[c] * rsqrtf(bnd2[192 + c] + 1e-5f);
    float hD2 = bnd2[64 + c] - bnd2[128 + c] * sD2;
    float sD3 = bnd3[c] * rsqrtf(bnd3[192 + c] + 1e-5f);
    float hD3 = bnd3[64 + c] - bnd3[128 + c] * sD3;
    float sST = bns[c] * rsqrtf(bns[192 + c] + 1e-5f);
    float hST = bns[64 + c] - bns[128 + c] * sST;
    float e0 = __expf(cw[0]), e1 = __expf(cw[1]), e2 = __expf(cw[2]);
    float inv = 1.f / (e0 + e1 + e2);
    float cw0 = e0 * inv, cw1 = e1 * inv, cw2 = e2 * inv;
    __syncthreads();

    for (int i = tid; i < 22 * 80; i += 256) {
        int rr = i / 80, col = i % 80;
        int gy = y0 - 3 + rr;
        float v = 0.f;
        if (gy >= 0 && gy < HH) {
            float a = 0.f;
#pragma unroll
            for (int k = 0; k < 7; k++) a = fmaf(wa1r[k], hst[rr][col + k], a);
            v = siluf(a * sA1 + hA1);
        }
        sa1[rr][col] = v;
    }
    __syncthreads();

    const float* dcnp = g_dcn + (size_t)bc * HW;
    float* starp = g_star + (size_t)bc * HW;
    float lsum = 0.f;
#pragma unroll
    for (int i = 0; i < 5; i++) {
        int col = xg + i;
        float d2 = 0.f, d3 = 0.f;
#pragma unroll
        for (int ky = 0; ky < 3; ky++)
#pragma unroll
            for (int kx = 0; kx < 3; kx++) {
                d2 = fmaf(wd2r[ky * 3 + kx], hst[r + 3 + 2 * (ky - 1)][col + 3 + 2 * (kx - 1)], d2);
                d3 = fmaf(wd3r[ky * 3 + kx], hst[r + 3 + 3 * (ky - 1)][col + 3 + 3 * (kx - 1)], d3);
            }
        float a2 = 0.f;
#pragma unroll
        for (int ky = 0; ky < 7; ky++) a2 = fmaf(wa2r[ky], sa1[r + ky][col], a2);
        float ctx = cw0 * siluf(d2 * sD2 + hD2)
                  + cw1 * siluf(d3 * sD3 + hD3)
                  + cw2 * siluf(a2 * sA2 + hA2);
        int p = (y0 + r) * WW + col;
        float st = (dcnp[p] * ctx) * sST + hST;
        starp[p] = st;
        lsum += st;
    }
    ssum[tid] = lsum;
    __syncthreads();
    for (int o = 128; o > 0; o >>= 1) {
        if (tid < o) ssum[tid] += ssum[tid + o];
        __syncthreads();
    }
    if (tid == 0) atomicAdd(&g_chmean[bc], ssum[0]);
}

// ---------------- K8: ECA conv1d(k=5,pad=2) + sigmoid ----------------
__global__ void k_eca(const float* __restrict__ ew) {
    int b = blockIdx.x;
    int c = threadIdx.x;
    __shared__ float sm[CS];
    sm[c] = g_chmean[b * CS + c] * (1.f / (float)HW);
    __syncthreads();
    float s = 0.f;
#pragma unroll
    for (int k = 0; k < 5; k++) {
        int cc = c - 2 + k;
        if (cc >= 0 && cc < CS) s = fmaf(ew[k], sm[cc], s);
    }
    g_ych[b * CS + c] = sigf(s);
}

// ---------------- K9: spatial mean/max (channel-quad split) ----------------
__global__ void __launch_bounds__(256)
k_spstat() {
    __shared__ float ys[CS];
    __shared__ float smean[4][64];
    __shared__ float smax[4][64];
    const int b = blockIdx.y;
    const int px = threadIdx.x & 63;
    const int q = threadIdx.x >> 6;
    const int p = blockIdx.x * 64 + px;
    if (threadIdx.x < CS) ys[threadIdx.x] = g_ych[b * CS + threadIdx.x];
    __syncthreads();
    float s = 0.f, mx = -3.4e38f;
    const float* base = g_star + ((size_t)b * CS + q * 16) * HW + p;
#pragma unroll 4
    for (int c = 0; c < 16; c++) {
        float v = base[(size_t)c * HW] * ys[q * 16 + c];
        s += v;
        mx = fmaxf(mx, v);
    }
    smean[q][px] = s;
    smax[q][px] = mx;
    __syncthreads();
    if (q == 0) {
#pragma unroll
        for (int k = 1; k < 4; k++) {
            s += smean[k][px];
            mx = fmaxf(mx, smax[k][px]);
        }
        g_spmean[(size_t)b * HW + p] = s * (1.f / (float)CS);
        g_spmax[(size_t)b * HW + p] = mx;
    }
}

// ---------------- K10: spatial attention conv 7x7 (2->1) + sigmoid (tiled) ----------------
__global__ void __launch_bounds__(256)
k_satt_t(const float* __restrict__ sw) {
    __shared__ float m0t[22][86];
    __shared__ float m1t[22][86];
    const int y0 = blockIdx.x * 16;
    const int b = blockIdx.y;
    const int tid = threadIdx.x;
    const int r = tid >> 4;
    const int xg = (tid & 15) * 5;

    const float* m0 = g_spmean + (size_t)b * HW;
    const float* m1 = g_spmax + (size_t)b * HW;
    for (int i = tid; i < 22 * 86; i += 256) {
        int rr = i / 86, col = i % 86;
        int gy = y0 - 3 + rr, gx = col - 3;
        float v0 = 0.f, v1 = 0.f;
        if (gy >= 0 && gy < HH && gx >= 0 && gx < WW) {
            v0 = m0[gy * WW + gx];
            v1 = m1[gy * WW + gx];
        }
        m0t[rr][col] = v0;
        m1t[rr][col] = v1;
    }
    __syncthreads();
    float* dst = g_satt + (size_t)b * HW + (y0 + r) * WW + xg;
#pragma unroll
    for (int i = 0; i < 5; i++) {
        float s = 0.f;
#pragma unroll
        for (int ky = 0; ky < 7; ky++)
#pragma unroll
            for (int kx = 0; kx < 7; kx++) {
                s = fmaf(sw[ky * 7 + kx], m0t[r + ky][xg + i + kx], s);
                s = fmaf(sw[49 + ky * 7 + kx], m1t[r + ky][xg + i + kx], s);
            }
        dst[i] = sigf(s);
    }
}

// ---------------- K11: expand 1x1 (128->256) + BN + SiLU + residual via mma.sync ----------------
__global__ void __launch_bounds__(256, 2)
k_expand_mma(const float* __restrict__ x, const float* __restrict__ bne,
             const float* __restrict__ bw, float* __restrict__ out) {
    extern __shared__ char sm[];
    const int b = blockIdx.y;
    const int p0 = blockIdx.x * 128;
    const int oc0 = blockIdx.z * 128;
    const int tid = threadIdx.x;
    const int wid = tid >> 5;
    const int lane = tid & 31;
    const int g = lane >> 2, t = lane & 3;
    const int warp_m = wid >> 1;
    const int warp_n = wid & 1;

    const float alpha = 1.f / (1.f + __expf(-bw[0]));
    const float oma = 1.f - alpha;

    float c[2][8][4];
#pragma unroll
    for (int mf = 0; mf < 2; mf++)
#pragma unroll
        for (int nf = 0; nf < 8; nf++)
#pragma unroll
            for (int i = 0; i < 4; i++) c[mf][nf][i] = 0.f;

    for (int kc = 0; kc < 2; kc++) {
#pragma unroll
        for (int i = 0; i < 16; i++) {
            int p = i * 256 + tid;
            int oc = p >> 5, j = p & 31;
            int q = (oc0 + oc) * 64 + kc * 32 + j;
            *(uint32_t*)(sm + OFF_A_HI + oc * TSTRIDE + j * 4) = g_wexp_h[q];
            *(uint32_t*)(sm + OFF_A_LO + oc * TSTRIDE + j * 4) = g_wexp_l[q];
        }
#pragma unroll
        for (int i = 0; i < 16; i++) {
            int p = i * 256 + tid;
            int px = p & 127, kp = p >> 7;
            int ch = kc * 32 + kp;
            float v0 = g_star[((size_t)b * CS + ch) * HW + p0 + px]
                     * g_ych[b * CS + ch]
                     * g_satt[(size_t)b * HW + p0 + px] * alpha;
            float v1 = g_h[((size_t)b * CMID + CS + ch) * HW + p0 + px] * oma;
            uint32_t hi, lo;
            split2(v0, v1, hi, lo);
            *(uint32_t*)(sm + OFF_B_HI + px * TSTRIDE + kp * 4) = hi;
            *(uint32_t*)(sm + OFF_B_LO + px * TSTRIDE + kp * 4) = lo;
        }
        __syncthreads();
#pragma unroll
        for (int ks = 0; ks < 4; ks++) {
            const int kk = ks * 16;
            uint32_t ahi[2][4], alo[2][4];
#pragma unroll
            for (int mf = 0; mf < 2; mf++) {
                int r0 = warp_m * 32 + mf * 16;
                const char* ph = sm + OFF_A_HI + (r0 + g) * TSTRIDE + (kk + 2 * t) * 2;
                ahi[mf][0] = *(const uint32_t*)(ph);
                ahi[mf][1] = *(const uint32_t*)(ph + 8 * TSTRIDE);
                ahi[mf][2] = *(const uint32_t*)(ph + 16);
                ahi[mf][3] = *(const uint32_t*)(ph + 8 * TSTRIDE + 16);
                const char* pl = sm + OFF_A_LO + (r0 + g) * TSTRIDE + (kk + 2 * t) * 2;
                alo[mf][0] = *(const uint32_t*)(pl);
                alo[mf][1] = *(const uint32_t*)(pl + 8 * TSTRIDE);
                alo[mf][2] = *(const uint32_t*)(pl + 16);
                alo[mf][3] = *(const uint32_t*)(pl + 8 * TSTRIDE + 16);
            }
            uint32_t bhi[8][2], blo[8][2];
#pragma unroll
            for (int nf = 0; nf < 8; nf++) {
                int n0 = warp_n * 64 + nf * 8;
                const char* ph = sm + OFF_B_HI + (n0 + g) * TSTRIDE + (kk + 2 * t) * 2;
                bhi[nf][0] = *(const uint32_t*)(ph);
                bhi[nf][1] = *(const uint32_t*)(ph + 16);
                const char* pl = sm + OFF_B_LO + (n0 + g) * TSTRIDE + (kk + 2 * t) * 2;
                blo[nf][0] = *(const uint32_t*)(pl);
                blo[nf][1] = *(const uint32_t*)(pl + 16);
            }
#pragma unroll
            for (int mf = 0; mf < 2; mf++)
#pragma unroll
                for (int nf = 0; nf < 8; nf++) {
                    mma16816(c[mf][nf], ahi[mf], bhi[nf]);
                    mma16816(c[mf][nf], ahi[mf], blo[nf]);
                    mma16816(c[mf][nf], alo[mf], bhi[nf]);
                }
        }
        __syncthreads();
    }

#pragma unroll
    for (int mf = 0; mf < 2; mf++) {
        int ocA = oc0 + warp_m * 32 + mf * 16 + g;
        int ocB = ocA + 8;
        float gA = bne[ocA], bA = bne[256 + ocA], mA = bne[512 + ocA], vA = bne[768 + ocA];
        float sA = gA * rsqrtf(vA + 1e-5f), shA = bA - mA * sA;
        float gB = bne[ocB], bB = bne[256 + ocB], mB = bne[512 + ocB], vB = bne[768 + ocB];
        float sB = gB * rsqrtf(vB + 1e-5f), shB = bB - mB * sB;
        float* dA = out + ((size_t)b * C1 + ocA) * HW + p0 + warp_n * 64;
        float* dB = out + ((size_t)b * C1 + ocB) * HW + p0 + warp_n * 64;
        const float* rA = x + ((size_t)b * C1 + ocA) * HW + p0 + warp_n * 64;
        const float* rB = x + ((size_t)b * C1 + ocB) * HW + p0 + warp_n * 64;
#pragma unroll
        for (int nf = 0; nf < 8; nf++) {
            int px = nf * 8 + 2 * t;
            float2 resA = *(const float2*)(rA + px);
            float2 resB = *(const float2*)(rB + px);
            *(float2*)(dA + px) = make_float2(siluf(c[mf][nf][0] * sA + shA) + resA.x,
                                              siluf(c[mf][nf][1] * sA + shA) + resA.y);
            *(float2*)(dB + px) = make_float2(siluf(c[mf][nf][2] * sB + shB) + resB.x,
                                              siluf(c[mf][nf][3] * sB + shB) + resB.y);
        }
    }
}

// ---------------- launch ----------------
extern "C" void kernel_launch(void* const* d_in, const int* in_sizes, int n_in,
                              void* d_out, int out_size) {
    const float* x          = (const float*)d_in[0];
    const float* w_reduce   = (const float*)d_in[1];
    const float* bn_reduce  = (const float*)d_in[2];
    const float* dcn_off_w  = (const float*)d_in[3];
    const float* dcn_off_b  = (const float*)d_in[4];
    const float* dcn_dw_w   = (const float*)d_in[5];
    const float* dcn_pw_w   = (const float*)d_in[6];
    const float* bn_dcn     = (const float*)d_in[7];
    const float* w_d2       = (const float*)d_in[8];
    const float* bn_d2      = (const float*)d_in[9];
    const float* w_d3       = (const float*)d_in[10];
    const float* bn_d3      = (const float*)d_in[11];
    const float* w_asym1    = (const float*)d_in[12];
    const float* bn_asym1   = (const float*)d_in[13];
    const float* w_asym2    = (const float*)d_in[14];
    const float* bn_asym2   = (const float*)d_in[15];
    const float* ctx_weight = (const float*)d_in[16];
    const float* bn_star    = (const float*)d_in[17];
    const float* eca_w      = (const float*)d_in[18];
    const float* sp_w       = (const float*)d_in[19];
    const float* blend_w    = (const float*)d_in[20];
    const float* w_expand   = (const float*)d_in[21];
    const float* bn_expand  = (const float*)d_in[22];
    float* out = (float*)d_out;

    static bool attr_done = false;
    if (!attr_done) {
        cudaFuncSetAttribute(k_reduce_mma, cudaFuncAttributeMaxDynamicSharedMemorySize, GEMM_SMEM);
        cudaFuncSetAttribute(k_expand_mma, cudaFuncAttributeMaxDynamicSharedMemorySize, GEMM_SMEM);
        cudaFuncSetAttribute(k_pw_mma, cudaFuncAttributeMaxDynamicSharedMemorySize, PW_SMEM);
        attr_done = true;
    }

    k_prepw<<<136, 256>>>(w_reduce, w_expand, dcn_pw_w);
    k_reduce_mma<<<dim3(HW / 128, BB), 256, GEMM_SMEM>>>(x, bn_reduce);
    k_offconv_t<<<dim3(NGRP, 5, BB), 256>>>(dcn_off_w);
    k_omsum<<<dim3(HW / 256, BB), 256>>>(dcn_off_b);
    k_sample_t<<<dim3(HW / 256, BB, 4), 256>>>();
    k_dw3x3_t<<<dim3(5, BB * CS), 256>>>(dcn_dw_w);
    k_pw_mma<<<dim3(HW / 128, BB), 256, PW_SMEM>>>(bn_dcn);
    k_ctx_star<<<dim3(5, BB * CS), 256>>>(w_d2, bn_d2, w_d3, bn_d3,
                                          w_asym1, bn_asym1, w_asym2, bn_asym2,
                                          ctx_weight, bn_star);
    k_eca<<<BB, CS>>>(eca_w);
    k_spstat<<<dim3(HW / 64, BB), 256>>>();
    k_satt_t<<<dim3(5, BB), 256>>>(sp_w);
    k_expand_mma<<<dim3(HW / 128, BB, 2), 256, GEMM_SMEM>>>(x, bn_expand, blend_w, out);
}

// round 13
// speedup vs baseline: 1.6071x; 1.0221x over previous
#include <cuda_runtime.h>
#include <cuda_bf16.h>
#include <cstdint>

#define BB 16
#define C1 256
#define CMID 128
#define CS 64
#define HH 80
#define WW 80
#define HW 6400
#define NGRP 32

// ---------------- scratch (device globals; no allocations) ----------------
__device__ float g_h[(size_t)BB*CMID*HW];     // reduce output (hs ch 0..63, hb 64..127)
__device__ float g_omp[(size_t)NGRP*BB*3*HW]; // offset conv partials (32 channel groups)
__device__ float4 g_spw[(size_t)BB*HW];       // bilinear weights (mask folded)
__device__ int4   g_spi[(size_t)BB*HW];       // gather indices (clamped)
__device__ float g_xd[(size_t)BB*CS*HW];      // grid-sampled * mask
__device__ float g_t1[(size_t)BB*CS*HW];      // dcn depthwise out
__device__ float g_dcn[(size_t)BB*CS*HW];     // dcn branch
__device__ float g_star[(size_t)BB*CS*HW];    // star0 = bn_star(dcn*ctx)
__device__ float g_chmean[BB*CS];             // raw channel sums (atomic)
__device__ float g_ych[BB*CS];
__device__ float g_spmean[(size_t)BB*HW];
__device__ float g_spmax[(size_t)BB*HW];
__device__ float g_satt[(size_t)BB*HW];
// pre-split bf16 hi/lo weights (k-pair packed)
__device__ uint32_t g_wred_h[128*128], g_wred_l[128*128];
__device__ uint32_t g_wexp_h[256*64],  g_wexp_l[256*64];
__device__ uint32_t g_wpw_h[64*32],    g_wpw_l[64*32];

__device__ __forceinline__ float siluf(float v) { return v / (1.f + __expf(-v)); }
__device__ __forceinline__ float sigf(float v)  { return 1.f / (1.f + __expf(-v)); }

// ---------------- mma.sync helpers ----------------
__device__ __forceinline__ void mma16816(float* c, const uint32_t* a, const uint32_t* b) {
    asm volatile(
        "mma.sync.aligned.m16n8k16.row.col.f32.bf16.bf16.f32 "
        "{%0,%1,%2,%3}, {%4,%5,%6,%7}, {%8,%9}, {%0,%1,%2,%3};"
        : "+f"(c[0]), "+f"(c[1]), "+f"(c[2]), "+f"(c[3])
        : "r"(a[0]), "r"(a[1]), "r"(a[2]), "r"(a[3]), "r"(b[0]), "r"(b[1]));
}

// truncation split: hi = exact top-16-bit bf16 pair (PRMT), lo = rounded residual pair
__device__ __forceinline__ void split2(float v0, float v1, uint32_t& hi, uint32_t& lo) {
    uint32_t b0 = __float_as_uint(v0), b1 = __float_as_uint(v1);
    asm("prmt.b32 %0, %1, %2, 0x7632;" : "=r"(hi) : "r"(b0), "r"(b1));
    float h0 = __uint_as_float(b0 & 0xFFFF0000u);
    float h1 = __uint_as_float(b1 & 0xFFFF0000u);
    __nv_bfloat162 tl = __floats2bfloat162_rn(v0 - h0, v1 - h1);
    lo = *(uint32_t*)&tl;
}

#define TSTRIDE 144
#define TILE_BYTES (128 * TSTRIDE)           // 18432
#define OFF_A_HI 0
#define OFF_A_LO TILE_BYTES
#define OFF_B_HI (2 * TILE_BYTES)
#define OFF_B_LO (3 * TILE_BYTES)
#define GEMM_SMEM (4 * TILE_BYTES)           // 73728

#define PW_A_HI 0
#define PW_A_LO (64 * TSTRIDE)
#define PW_B_HI (2 * 64 * TSTRIDE)
#define PW_B_LO (PW_B_HI + 128 * TSTRIDE)
#define PW_SMEM (PW_B_LO + 128 * TSTRIDE)    // 55296

// ---------------- K0: zero accumulators + pre-split GEMM weights ----------------
__global__ void k_prepw(const float* __restrict__ wred, const float* __restrict__ wexp,
                        const float* __restrict__ wpw) {
    int idx = blockIdx.x * 256 + threadIdx.x;   // 0..34815
    if (idx < 1024) g_chmean[idx] = 0.f;
    if (idx < 16384) {
        int oc = idx >> 7, j = idx & 127;
        split2(wred[oc * 256 + 2 * j], wred[oc * 256 + 2 * j + 1],
               g_wred_h[idx], g_wred_l[idx]);
    } else if (idx < 32768) {
        int q = idx - 16384;
        int oc = q >> 6, j = q & 63;
        split2(wexp[oc * 128 + 2 * j], wexp[oc * 128 + 2 * j + 1],
               g_wexp_h[q], g_wexp_l[q]);
    } else {
        int q = idx - 32768;
        int oc = q >> 5, j = q & 31;
        split2(wpw[oc * 64 + 2 * j], wpw[oc * 64 + 2 * j + 1],
               g_wpw_h[q], g_wpw_l[q]);
    }
}

// ---------------- K1: reduce 1x1 (256->128) + BN + SiLU via mma.sync bf16x3 ----------------
__global__ void __launch_bounds__(256, 2)
k_reduce_mma(const float* __restrict__ x, const float* __restrict__ bnr) {
    extern __shared__ char sm[];
    const int b = blockIdx.y;
    const int p0 = blockIdx.x * 128;
    const int tid = threadIdx.x;
    const int wid = tid >> 5;
    const int lane = tid & 31;
    const int g = lane >> 2, t = lane & 3;
    const int warp_m = wid >> 1;
    const int warp_n = wid & 1;

    float c[2][8][4];
#pragma unroll
    for (int mf = 0; mf < 2; mf++)
#pragma unroll
        for (int nf = 0; nf < 8; nf++)
#pragma unroll
            for (int i = 0; i < 4; i++) c[mf][nf][i] = 0.f;

    const float* xb = x + (size_t)b * C1 * HW + p0;

    for (int kc = 0; kc < 4; kc++) {
#pragma unroll
        for (int i = 0; i < 16; i++) {
            int p = i * 256 + tid;
            int oc = p >> 5, j = p & 31;
            int q = oc * 128 + kc * 32 + j;
            *(uint32_t*)(sm + OFF_A_HI + oc * TSTRIDE + j * 4) = g_wred_h[q];
            *(uint32_t*)(sm + OFF_A_LO + oc * TSTRIDE + j * 4) = g_wred_l[q];
        }
#pragma unroll
        for (int i = 0; i < 16; i++) {
            int p = i * 256 + tid;
            int px = p & 127, kp = p >> 7;
            const float* src = xb + (size_t)(kc * 64 + 2 * kp) * HW + px;
            uint32_t hi, lo;
            split2(src[0], src[HW], hi, lo);
            *(uint32_t*)(sm + OFF_B_HI + px * TSTRIDE + kp * 4) = hi;
            *(uint32_t*)(sm + OFF_B_LO + px * TSTRIDE + kp * 4) = lo;
        }
        __syncthreads();
#pragma unroll
        for (int ks = 0; ks < 4; ks++) {
            const int kk = ks * 16;
            uint32_t ahi[2][4], alo[2][4];
#pragma unroll
            for (int mf = 0; mf < 2; mf++) {
                int r0 = warp_m * 32 + mf * 16;
                const char* ph = sm + OFF_A_HI + (r0 + g) * TSTRIDE + (kk + 2 * t) * 2;
                ahi[mf][0] = *(const uint32_t*)(ph);
                ahi[mf][1] = *(const uint32_t*)(ph + 8 * TSTRIDE);
                ahi[mf][2] = *(const uint32_t*)(ph + 16);
                ahi[mf][3] = *(const uint32_t*)(ph + 8 * TSTRIDE + 16);
                const char* pl = sm + OFF_A_LO + (r0 + g) * TSTRIDE + (kk + 2 * t) * 2;
                alo[mf][0] = *(const uint32_t*)(pl);
                alo[mf][1] = *(const uint32_t*)(pl + 8 * TSTRIDE);
                alo[mf][2] = *(const uint32_t*)(pl + 16);
                alo[mf][3] = *(const uint32_t*)(pl + 8 * TSTRIDE + 16);
            }
            uint32_t bhi[8][2], blo[8][2];
#pragma unroll
            for (int nf = 0; nf < 8; nf++) {
                int n0 = warp_n * 64 + nf * 8;
                const char* ph = sm + OFF_B_HI + (n0 + g) * TSTRIDE + (kk + 2 * t) * 2;
                bhi[nf][0] = *(const uint32_t*)(ph);
                bhi[nf][1] = *(const uint32_t*)(ph + 16);
                const char* pl = sm + OFF_B_LO + (n0 + g) * TSTRIDE + (kk + 2 * t) * 2;
                blo[nf][0] = *(const uint32_t*)(pl);
                blo[nf][1] = *(const uint32_t*)(pl + 16);
            }
#pragma unroll
            for (int mf = 0; mf < 2; mf++)
#pragma unroll
                for (int nf = 0; nf < 8; nf++) {
                    mma16816(c[mf][nf], ahi[mf], bhi[nf]);
                    mma16816(c[mf][nf], ahi[mf], blo[nf]);
                    mma16816(c[mf][nf], alo[mf], bhi[nf]);
                }
        }
        __syncthreads();
    }

#pragma unroll
    for (int mf = 0; mf < 2; mf++) {
        int ocA = warp_m * 32 + mf * 16 + g;
        int ocB = ocA + 8;
        float gA = bnr[ocA], bA = bnr[128 + ocA], mA = bnr[256 + ocA], vA = bnr[384 + ocA];
        float sA = gA * rsqrtf(vA + 1e-5f), shA = bA - mA * sA;
        float gB = bnr[ocB], bB = bnr[128 + ocB], mB = bnr[256 + ocB], vB = bnr[384 + ocB];
        float sB = gB * rsqrtf(vB + 1e-5f), shB = bB - mB * sB;
        float* dA = g_h + ((size_t)b * CMID + ocA) * HW + p0 + warp_n * 64;
        float* dB = g_h + ((size_t)b * CMID + ocB) * HW + p0 + warp_n * 64;
#pragma unroll
        for (int nf = 0; nf < 8; nf++) {
            int px = nf * 8 + 2 * t;
            *(float2*)(dA + px) = make_float2(siluf(c[mf][nf][0] * sA + shA),
                                              siluf(c[mf][nf][1] * sA + shA));
            *(float2*)(dB + px) = make_float2(siluf(c[mf][nf][2] * sB + shB),
                                              siluf(c[mf][nf][3] * sB + shB));
        }
    }
}

// ---------------- K2: offset conv 3x3 (2-ch group partials, 32 groups) ----------------
__global__ void __launch_bounds__(256)
k_offconv_t(const float* __restrict__ wo) {
    __shared__ float tile[18][82];
    __shared__ float sw[3][2][9];
    const int grp = blockIdx.x;
    const int y0 = blockIdx.y * 16;
    const int b = blockIdx.z;
    const int tid = threadIdx.x;
    const int r = tid >> 4;
    const int xg = (tid & 15) * 5;

    if (tid < 3 * 2 * 9) {
        int o = tid / 18, rest = tid % 18;
        int cc = rest / 9, k = rest % 9;
        sw[o][cc][k] = wo[o * 576 + (grp * 2 + cc) * 9 + k];
    }

    float acc[3][5];
#pragma unroll
    for (int o = 0; o < 3; o++)
#pragma unroll
        for (int i = 0; i < 5; i++) acc[o][i] = 0.f;

    __syncthreads();
    for (int cc = 0; cc < 2; cc++) {
        const float* im = g_h + ((size_t)b * CMID + grp * 2 + cc) * HW;
        for (int i = tid; i < 18 * 82; i += 256) {
            int rr = i / 82, col = i % 82;
            int gy = y0 - 1 + rr, gx = col - 1;
            float v = 0.f;
            if (gy >= 0 && gy < HH && gx >= 0 && gx < WW) v = im[gy * WW + gx];
            tile[rr][col] = v;
        }
        __syncthreads();
#pragma unroll
        for (int ky = 0; ky < 3; ky++) {
            float s[7];
#pragma unroll
            for (int j = 0; j < 7; j++) s[j] = tile[r + ky][xg + j];
#pragma unroll
            for (int o = 0; o < 3; o++) {
                float w0 = sw[o][cc][ky * 3 + 0];
                float w1 = sw[o][cc][ky * 3 + 1];
                float w2 = sw[o][cc][ky * 3 + 2];
#pragma unroll
                for (int i = 0; i < 5; i++) {
                    acc[o][i] = fmaf(w0, s[i], acc[o][i]);
                    acc[o][i] = fmaf(w1, s[i + 1], acc[o][i]);
                    acc[o][i] = fmaf(w2, s[i + 2], acc[o][i]);
                }
            }
        }
        __syncthreads();
    }
    float* dst = g_omp + ((size_t)grp * BB + b) * 3 * HW;
#pragma unroll
    for (int o = 0; o < 3; o++)
#pragma unroll
        for (int i = 0; i < 5; i++)
            dst[o * HW + (y0 + r) * WW + xg + i] = acc[o][i];
}

// ---------------- K3: sum offset partials (4-quad split) + bake sampling params ----------------
__global__ void __launch_bounds__(256)
k_omsum(const float* __restrict__ bo) {
    __shared__ float psum[3][4][64];
    const int px = threadIdx.x & 63;
    const int q = threadIdx.x >> 6;
    const int p = blockIdx.x * 64 + px;
    const int b = blockIdx.y;

    float s0 = 0.f, s1 = 0.f, s2 = 0.f;
#pragma unroll
    for (int g = 0; g < 8; g++) {
        int grp = q * 8 + g;
        const float* src = g_omp + ((size_t)grp * BB + b) * 3 * HW + p;
        s0 += src[0];
        s1 += src[HW];
        s2 += src[2 * HW];
    }
    psum[0][q][px] = s0;
    psum[1][q][px] = s1;
    psum[2][q][px] = s2;
    __syncthreads();
    if (q == 0) {
        float om0 = bo[0] + s0 + psum[0][1][px] + psum[0][2][px] + psum[0][3][px];
        float om1 = bo[1] + s1 + psum[1][1][px] + psum[1][2][px] + psum[1][3][px];
        float om2 = bo[2] + s2 + psum[2][1][px] + psum[2][2][px] + psum[2][3][px];
        int xx = p % WW, yy = p / WW;
        float mk = sigf(om2);
        float linx = -1.f + 2.f * xx / (WW - 1);
        float liny = -1.f + 2.f * yy / (HH - 1);
        float gx = (linx + om1 * (2.f / WW) + 1.f) * 0.5f * (WW - 1);
        float gy = (liny + om0 * (2.f / HH) + 1.f) * 0.5f * (HH - 1);
        float x0f = floorf(gx), y0f = floorf(gy);
        float wx = gx - x0f, wy = gy - y0f;
        int x0 = (int)x0f, y0 = (int)y0f;
        bool vx0 = (x0 >= 0 && x0 < WW), vx1 = (x0 + 1 >= 0 && x0 + 1 < WW);
        bool vy0 = (y0 >= 0 && y0 < HH), vy1 = (y0 + 1 >= 0 && y0 + 1 < HH);
        int cx0 = min(max(x0, 0), WW - 1), cx1 = min(max(x0 + 1, 0), WW - 1);
        int cy0 = min(max(y0, 0), HH - 1), cy1 = min(max(y0 + 1, 0), HH - 1);
        float4 w;
        w.x = (1.f - wx) * (1.f - wy) * mk * (vx0 && vy0 ? 1.f : 0.f);
        w.y = wx * (1.f - wy) * mk * (vx1 && vy0 ? 1.f : 0.f);
        w.z = (1.f - wx) * wy * mk * (vx0 && vy1 ? 1.f : 0.f);
        w.w = wx * wy * mk * (vx1 && vy1 ? 1.f : 0.f);
        int4 ix;
        ix.x = cy0 * WW + cx0;
        ix.y = cy0 * WW + cx1;
        ix.z = cy1 * WW + cx0;
        ix.w = cy1 * WW + cx1;
        g_spw[(size_t)b * HW + p] = w;
        g_spi[(size_t)b * HW + p] = ix;
    }
}

// ---------------- K4: grid sample * mask (params precomputed, channel-split z=4) ----------------
__global__ void __launch_bounds__(256)
k_sample_t() {
    const int p = blockIdx.x * 256 + threadIdx.x;
    const int b = blockIdx.y;
    const int c0 = blockIdx.z * 16;

    float4 w = g_spw[(size_t)b * HW + p];
    int4 ix = g_spi[(size_t)b * HW + p];

    const float* im = g_h + ((size_t)b * CMID + c0) * HW;
    float* dst = g_xd + ((size_t)b * CS + c0) * HW + p;
#pragma unroll 4
    for (int c = 0; c < 16; c++) {
        const float* pl = im + (size_t)c * HW;
        float r = w.x * pl[ix.x] + w.y * pl[ix.y] + w.z * pl[ix.z] + w.w * pl[ix.w];
        dst[(size_t)c * HW] = r;
    }
}

// ---------------- K5: depthwise 3x3 pad1 on xd (tiled) ----------------
__global__ void __launch_bounds__(256)
k_dw3x3_t(const float* __restrict__ wdw) {
    __shared__ float tile[18][82];
    const int y0 = blockIdx.x * 16;
    const int bc = blockIdx.y;
    const int c = bc & 63;
    const int tid = threadIdx.x;
    const int r = tid >> 4;
    const int xg = (tid & 15) * 5;

    const float* im = g_xd + (size_t)bc * HW;
    for (int i = tid; i < 18 * 82; i += 256) {
        int rr = i / 82, col = i % 82;
        int gy = y0 - 1 + rr, gx = col - 1;
        float v = 0.f;
        if (gy >= 0 && gy < HH && gx >= 0 && gx < WW) v = im[gy * WW + gx];
        tile[rr][col] = v;
    }
    float w[9];
#pragma unroll
    for (int k = 0; k < 9; k++) w[k] = wdw[c * 9 + k];
    __syncthreads();

    float acc[5] = {0.f, 0.f, 0.f, 0.f, 0.f};
#pragma unroll
    for (int ky = 0; ky < 3; ky++) {
        float s[7];
#pragma unroll
        for (int j = 0; j < 7; j++) s[j] = tile[r + ky][xg + j];
#pragma unroll
        for (int i = 0; i < 5; i++)
#pragma unroll
            for (int kx = 0; kx < 3; kx++)
                acc[i] = fmaf(w[ky * 3 + kx], s[i + kx], acc[i]);
    }
    float* dst = g_t1 + (size_t)bc * HW + (y0 + r) * WW + xg;
#pragma unroll
    for (int i = 0; i < 5; i++) dst[i] = acc[i];
}

// ---------------- K6: pw 1x1 (64->64) + BN + SiLU via mma.sync bf16x3 ----------------
__global__ void __launch_bounds__(256, 3)
k_pw_mma(const float* __restrict__ bnp) {
    extern __shared__ char sm[];
    const int b = blockIdx.y;
    const int p0 = blockIdx.x * 128;
    const int tid = threadIdx.x;
    const int wid = tid >> 5;
    const int lane = tid & 31;
    const int g = lane >> 2, t = lane & 3;
    const int warp_m = wid >> 2;
    const int warp_n = wid & 3;

    float c[2][4][4];
#pragma unroll
    for (int mf = 0; mf < 2; mf++)
#pragma unroll
        for (int nf = 0; nf < 4; nf++)
#pragma unroll
            for (int i = 0; i < 4; i++) c[mf][nf][i] = 0.f;

#pragma unroll
    for (int i = 0; i < 8; i++) {
        int p = i * 256 + tid;
        int oc = p >> 5, j = p & 31;
        *(uint32_t*)(sm + PW_A_HI + oc * TSTRIDE + j * 4) = g_wpw_h[p];
        *(uint32_t*)(sm + PW_A_LO + oc * TSTRIDE + j * 4) = g_wpw_l[p];
    }
    const float* tb = g_t1 + (size_t)b * CS * HW + p0;
#pragma unroll
    for (int i = 0; i < 16; i++) {
        int p = i * 256 + tid;
        int px = p & 127, kp = p >> 7;
        const float* src = tb + (size_t)(2 * kp) * HW + px;
        uint32_t hi, lo;
        split2(src[0], src[HW], hi, lo);
        *(uint32_t*)(sm + PW_B_HI + px * TSTRIDE + kp * 4) = hi;
        *(uint32_t*)(sm + PW_B_LO + px * TSTRIDE + kp * 4) = lo;
    }
    __syncthreads();
#pragma unroll
    for (int ks = 0; ks < 4; ks++) {
        const int kk = ks * 16;
        uint32_t ahi[2][4], alo[2][4];
#pragma unroll
        for (int mf = 0; mf < 2; mf++) {
            int r0 = warp_m * 32 + mf * 16;
            const char* ph = sm + PW_A_HI + (r0 + g) * TSTRIDE + (kk + 2 * t) * 2;
            ahi[mf][0] = *(const uint32_t*)(ph);
            ahi[mf][1] = *(const uint32_t*)(ph + 8 * TSTRIDE);
            ahi[mf][2] = *(const uint32_t*)(ph + 16);
            ahi[mf][3] = *(const uint32_t*)(ph + 8 * TSTRIDE + 16);
            const char* pl = sm + PW_A_LO + (r0 + g) * TSTRIDE + (kk + 2 * t) * 2;
            alo[mf][0] = *(const uint32_t*)(pl);
            alo[mf][1] = *(const uint32_t*)(pl + 8 * TSTRIDE);
            alo[mf][2] = *(const uint32_t*)(pl + 16);
            alo[mf][3] = *(const uint32_t*)(pl + 8 * TSTRIDE + 16);
        }
        uint32_t bhi[4][2], blo[4][2];
#pragma unroll
        for (int nf = 0; nf < 4; nf++) {
            int n0 = warp_n * 32 + nf * 8;
            const char* ph = sm + PW_B_HI + (n0 + g) * TSTRIDE + (kk + 2 * t) * 2;
            bhi[nf][0] = *(const uint32_t*)(ph);
            bhi[nf][1] = *(const uint32_t*)(ph + 16);
            const char* pl = sm + PW_B_LO + (n0 + g) * TSTRIDE + (kk + 2 * t) * 2;
            blo[nf][0] = *(const uint32_t*)(pl);
            blo[nf][1] = *(const uint32_t*)(pl + 16);
        }
#pragma unroll
        for (int mf = 0; mf < 2; mf++)
#pragma unroll
            for (int nf = 0; nf < 4; nf++) {
                mma16816(c[mf][nf], ahi[mf], bhi[nf]);
                mma16816(c[mf][nf], ahi[mf], blo[nf]);
                mma16816(c[mf][nf], alo[mf], bhi[nf]);
            }
    }

#pragma unroll
    for (int mf = 0; mf < 2; mf++) {
        int ocA = warp_m * 32 + mf * 16 + g;
        int ocB = ocA + 8;
        float gA = bnp[ocA], bA = bnp[64 + ocA], mA = bnp[128 + ocA], vA = bnp[192 + ocA];
        float sA = gA * rsqrtf(vA + 1e-5f), shA = bA - mA * sA;
        float gB = bnp[ocB], bB = bnp[64 + ocB], mB = bnp[128 + ocB], vB = bnp[192 + ocB];
        float sB = gB * rsqrtf(vB + 1e-5f), shB = bB - mB * sB;
        float* dA = g_dcn + ((size_t)b * CS + ocA) * HW + p0 + warp_n * 32;
        float* dB = g_dcn + ((size_t)b * CS + ocB) * HW + p0 + warp_n * 32;
#pragma unroll
        for (int nf = 0; nf < 4; nf++) {
            int px = nf * 8 + 2 * t;
            *(float2*)(dA + px) = make_float2(siluf(c[mf][nf][0] * sA + shA),
                                              siluf(c[mf][nf][1] * sA + shA));
            *(float2*)(dB + px) = make_float2(siluf(c[mf][nf][2] * sB + shB),
                                              siluf(c[mf][nf][3] * sB + shB));
        }
    }
}

// ---------------- K7: fused d2 + d3 + asym1 + asym2 + ctx blend + star + chmean ----------------
__global__ void __launch_bounds__(256)
k_ctx_star(const float* __restrict__ wd2, const float* __restrict__ bnd2,
           const float* __restrict__ wd3, const float* __restrict__ bnd3,
           const float* __restrict__ wa1, const float* __restrict__ bna1,
           const float* __restrict__ wa2, const float* __restrict__ bna2,
           const float* __restrict__ cw, const float* __restrict__ bns) {
    __shared__ float hst[22][86];
    __shared__ float sa1[22][80];
    __shared__ float ssum[256];
    const int y0 = blockIdx.x * 16;
    const int bc = blockIdx.y;
    const int b = bc >> 6, c = bc & 63;
    const int tid = threadIdx.x;
    const int r = tid >> 4;
    const int xg = (tid & 15) * 5;

    const float* im = g_h + ((size_t)b * CMID + c) * HW;
    for (int i = tid; i < 22 * 86; i += 256) {
        int rr = i / 86, col = i % 86;
        int gy = y0 - 3 + rr, gx = col - 3;
        float v = 0.f;
        if (gy >= 0 && gy < HH && gx >= 0 && gx < WW) v = im[gy * WW + gx];
        hst[rr][col] = v;
    }
    float wa1r[7], wa2r[7], wd2r[9], wd3r[9];
#pragma unroll
    for (int k = 0; k < 7; k++) { wa1r[k] = wa1[c * 7 + k]; wa2r[k] = wa2[c * 7 + k]; }
#pragma unroll
    for (int k = 0; k < 9; k++) { wd2r[k] = wd2[c * 9 + k]; wd3r[k] = wd3[c * 9 + k]; }
    float sA1 = bna1[c] * rsqrtf(bna1[192 + c] + 1e-5f);
    float hA1 = bna1[64 + c] - bna1[128 + c] * sA1;
    float sA2 = bna2[c] * rsqrtf(bna2[192 + c] + 1e-5f);
    float hA2 = bna2[64 + c] - bna2[128 + c] * sA2;
    float sD2 = bnd2[c] * rsqrtf(bnd2[192 + c] + 1e-5f);
    float hD2 = bnd2[64 + c] - bnd2[128 + c] * sD2;
    float sD3 = bnd3[c] * rsqrtf(bnd3[192 + c] + 1e-5f);
    float hD3 = bnd3[64 + c] - bnd3[128 + c] * sD3;
    float sST = bns[c] * rsqrtf(bns[192 + c] + 1e-5f);
    float hST = bns[64 + c] - bns[128 + c] * sST;
    float e0 = __expf(cw[0]), e1 = __expf(cw[1]), e2 = __expf(cw[2]);
    float inv = 1.f / (e0 + e1 + e2);
    float cw0 = e0 * inv, cw1 = e1 * inv, cw2 = e2 * inv;
    __syncthreads();

    for (int i = tid; i < 22 * 80; i += 256) {
        int rr = i / 80, col = i % 80;
        int gy = y0 - 3 + rr;
        float v = 0.f;
        if (gy >= 0 && gy < HH) {
            float a = 0.f;
#pragma unroll
            for (int k = 0; k < 7; k++) a = fmaf(wa1r[k], hst[rr][col + k], a);
            v = siluf(a * sA1 + hA1);
        }
        sa1[rr][col] = v;
    }
    __syncthreads();

    const float* dcnp = g_dcn + (size_t)bc * HW;
    float* starp = g_star + (size_t)bc * HW;
    float lsum = 0.f;
#pragma unroll
    for (int i = 0; i < 5; i++) {
        int col = xg + i;
        float d2 = 0.f, d3 = 0.f;
#pragma unroll
        for (int ky = 0; ky < 3; ky++)
#pragma unroll
            for (int kx = 0; kx < 3; kx++) {
                d2 = fmaf(wd2r[ky * 3 + kx], hst[r + 3 + 2 * (ky - 1)][col + 3 + 2 * (kx - 1)], d2);
                d3 = fmaf(wd3r[ky * 3 + kx], hst[r + 3 + 3 * (ky - 1)][col + 3 + 3 * (kx - 1)], d3);
            }
        float a2 = 0.f;
#pragma unroll
        for (int ky = 0; ky < 7; ky++) a2 = fmaf(wa2r[ky], sa1[r + ky][col], a2);
        float ctx = cw0 * siluf(d2 * sD2 + hD2)
                  + cw1 * siluf(d3 * sD3 + hD3)
                  + cw2 * siluf(a2 * sA2 + hA2);
        int p = (y0 + r) * WW + col;
        float st = (dcnp[p] * ctx) * sST + hST;
        starp[p] = st;
        lsum += st;
    }
    ssum[tid] = lsum;
    __syncthreads();
    for (int o = 128; o > 0; o >>= 1) {
        if (tid < o) ssum[tid] += ssum[tid + o];
        __syncthreads();
    }
    if (tid == 0) atomicAdd(&g_chmean[bc], ssum[0]);
}

// ---------------- K8: spatial mean/max (channel-quad split) + in-block ECA ----------------
__global__ void __launch_bounds__(256)
k_spstat(const float* __restrict__ ew) {
    __shared__ float chm[CS];
    __shared__ float ys[CS];
    __shared__ float smean[4][64];
    __shared__ float smax[4][64];
    const int b = blockIdx.y;
    const int px = threadIdx.x & 63;
    const int q = threadIdx.x >> 6;
    const int p = blockIdx.x * 64 + px;
    if (threadIdx.x < CS) chm[threadIdx.x] = g_chmean[b * CS + threadIdx.x] * (1.f / (float)HW);
    __syncthreads();
    if (threadIdx.x < CS) {
        int c = threadIdx.x;
        float s = 0.f;
#pragma unroll
        for (int k = 0; k < 5; k++) {
            int cc = c - 2 + k;
            if (cc >= 0 && cc < CS) s = fmaf(ew[k], chm[cc], s);
        }
        float y = sigf(s);
        ys[c] = y;
        if (blockIdx.x == 0) g_ych[b * CS + c] = y;
    }
    __syncthreads();
    float s = 0.f, mx = -3.4e38f;
    const float* base = g_star + ((size_t)b * CS + q * 16) * HW + p;
#pragma unroll 4
    for (int c = 0; c < 16; c++) {
        float v = base[(size_t)c * HW] * ys[q * 16 + c];
        s += v;
        mx = fmaxf(mx, v);
    }
    smean[q][px] = s;
    smax[q][px] = mx;
    __syncthreads();
    if (q == 0) {
#pragma unroll
        for (int k = 1; k < 4; k++) {
            s += smean[k][px];
            mx = fmaxf(mx, smax[k][px]);
        }
        g_spmean[(size_t)b * HW + p] = s * (1.f / (float)CS);
        g_spmax[(size_t)b * HW + p] = mx;
    }
}

// ---------------- K9: spatial attention conv 7x7 (2->1) + sigmoid (tiled) ----------------
__global__ void __launch_bounds__(256)
k_satt_t(const float* __restrict__ sw) {
    __shared__ float m0t[22][86];
    __shared__ float m1t[22][86];
    const int y0 = blockIdx.x * 16;
    const int b = blockIdx.y;
    const int tid = threadIdx.x;
    const int r = tid >> 4;
    const int xg = (tid & 15) * 5;

    const float* m0 = g_spmean + (size_t)b * HW;
    const float* m1 = g_spmax + (size_t)b * HW;
    for (int i = tid; i < 22 * 86; i += 256) {
        int rr = i / 86, col = i % 86;
        int gy = y0 - 3 + rr, gx = col - 3;
        float v0 = 0.f, v1 = 0.f;
        if (gy >= 0 && gy < HH && gx >= 0 && gx < WW) {
            v0 = m0[gy * WW + gx];
            v1 = m1[gy * WW + gx];
        }
        m0t[rr][col] = v0;
        m1t[rr][col] = v1;
    }
    __syncthreads();
    float* dst = g_satt + (size_t)b * HW + (y0 + r) * WW + xg;
#pragma unroll
    for (int i = 0; i < 5; i++) {
        float s = 0.f;
#pragma unroll
        for (int ky = 0; ky < 7; ky++)
#pragma unroll
            for (int kx = 0; kx < 7; kx++) {
                s = fmaf(sw[ky * 7 + kx], m0t[r + ky][xg + i + kx], s);
                s = fmaf(sw[49 + ky * 7 + kx], m1t[r + ky][xg + i + kx], s);
            }
        dst[i] = sigf(s);
    }
}

// ---------------- K10: expand 1x1 (128->256) + BN + SiLU + residual via mma.sync ----------------
__global__ void __launch_bounds__(256, 2)
k_expand_mma(const float* __restrict__ x, const float* __restrict__ bne,
             const float* __restrict__ bw, float* __restrict__ out) {
    extern __shared__ char sm[];
    const int b = blockIdx.y;
    const int p0 = blockIdx.x * 128;
    const int oc0 = blockIdx.z * 128;
    const int tid = threadIdx.x;
    const int wid = tid >> 5;
    const int lane = tid & 31;
    const int g = lane >> 2, t = lane & 3;
    const int warp_m = wid >> 1;
    const int warp_n = wid & 1;

    const float alpha = 1.f / (1.f + __expf(-bw[0]));
    const float oma = 1.f - alpha;

    float c[2][8][4];
#pragma unroll
    for (int mf = 0; mf < 2; mf++)
#pragma unroll
        for (int nf = 0; nf < 8; nf++)
#pragma unroll
            for (int i = 0; i < 4; i++) c[mf][nf][i] = 0.f;

    for (int kc = 0; kc < 2; kc++) {
#pragma unroll
        for (int i = 0; i < 16; i++) {
            int p = i * 256 + tid;
            int oc = p >> 5, j = p & 31;
            int q = (oc0 + oc) * 64 + kc * 32 + j;
            *(uint32_t*)(sm + OFF_A_HI + oc * TSTRIDE + j * 4) = g_wexp_h[q];
            *(uint32_t*)(sm + OFF_A_LO + oc * TSTRIDE + j * 4) = g_wexp_l[q];
        }
#pragma unroll
        for (int i = 0; i < 16; i++) {
            int p = i * 256 + tid;
            int px = p & 127, kp = p >> 7;
            int ch = kc * 32 + kp;
            float v0 = g_star[((size_t)b * CS + ch) * HW + p0 + px]
                     * g_ych[b * CS + ch]
                     * g_satt[(size_t)b * HW + p0 + px] * alpha;
            float v1 = g_h[((size_t)b * CMID + CS + ch) * HW + p0 + px] * oma;
            uint32_t hi, lo;
            split2(v0, v1, hi, lo);
            *(uint32_t*)(sm + OFF_B_HI + px * TSTRIDE + kp * 4) = hi;
            *(uint32_t*)(sm + OFF_B_LO + px * TSTRIDE + kp * 4) = lo;
        }
        __syncthreads();
#pragma unroll
        for (int ks = 0; ks < 4; ks++) {
            const int kk = ks * 16;
            uint32_t ahi[2][4], alo[2][4];
#pragma unroll
            for (int mf = 0; mf < 2; mf++) {
                int r0 = warp_m * 32 + mf * 16;
                const char* ph = sm + OFF_A_HI + (r0 + g) * TSTRIDE + (kk + 2 * t) * 2;
                ahi[mf][0] = *(const uint32_t*)(ph);
                ahi[mf][1] = *(const uint32_t*)(ph + 8 * TSTRIDE);
                ahi[mf][2] = *(const uint32_t*)(ph + 16);
                ahi[mf][3] = *(const uint32_t*)(ph + 8 * TSTRIDE + 16);
                const char* pl = sm + OFF_A_LO + (r0 + g) * TSTRIDE + (kk + 2 * t) * 2;
                alo[mf][0] = *(const uint32_t*)(pl);
                alo[mf][1] = *(const uint32_t*)(pl + 8 * TSTRIDE);
                alo[mf][2] = *(const uint32_t*)(pl + 16);
                alo[mf][3] = *(const uint32_t*)(pl + 8 * TSTRIDE + 16);
            }
            uint32_t bhi[8][2], blo[8][2];
#pragma unroll
            for (int nf = 0; nf < 8; nf++) {
                int n0 = warp_n * 64 + nf * 8;
                const char* ph = sm + OFF_B_HI + (n0 + g) * TSTRIDE + (kk + 2 * t) * 2;
                bhi[nf][0] = *(const uint32_t*)(ph);
                bhi[nf][1] = *(const uint32_t*)(ph + 16);
                const char* pl = sm + OFF_B_LO + (n0 + g) * TSTRIDE + (kk + 2 * t) * 2;
                blo[nf][0] = *(const uint32_t*)(pl);
                blo[nf][1] = *(const uint32_t*)(pl + 16);
            }
#pragma unroll
            for (int mf = 0; mf < 2; mf++)
#pragma unroll
                for (int nf = 0; nf < 8; nf++) {
                    mma16816(c[mf][nf], ahi[mf], bhi[nf]);
                    mma16816(c[mf][nf], ahi[mf], blo[nf]);
                    mma16816(c[mf][nf], alo[mf], bhi[nf]);
                }
        }
        __syncthreads();
    }

#pragma unroll
    for (int mf = 0; mf < 2; mf++) {
        int ocA = oc0 + warp_m * 32 + mf * 16 + g;
        int ocB = ocA + 8;
        float gA = bne[ocA], bA = bne[256 + ocA], mA = bne[512 + ocA], vA = bne[768 + ocA];
        float sA = gA * rsqrtf(vA + 1e-5f), shA = bA - mA * sA;
        float gB = bne[ocB], bB = bne[256 + ocB], mB = bne[512 + ocB], vB = bne[768 + ocB];
        float sB = gB * rsqrtf(vB + 1e-5f), shB = bB - mB * sB;
        float* dA = out + ((size_t)b * C1 + ocA) * HW + p0 + warp_n * 64;
        float* dB = out + ((size_t)b * C1 + ocB) * HW + p0 + warp_n * 64;
        const float* rA = x + ((size_t)b * C1 + ocA) * HW + p0 + warp_n * 64;
        const float* rB = x + ((size_t)b * C1 + ocB) * HW + p0 + warp_n * 64;
#pragma unroll
        for (int nf = 0; nf < 8; nf++) {
            int px = nf * 8 + 2 * t;
            float2 resA = *(const float2*)(rA + px);
            float2 resB = *(const float2*)(rB + px);
            *(float2*)(dA + px) = make_float2(siluf(c[mf][nf][0] * sA + shA) + resA.x,
                                              siluf(c[mf][nf][1] * sA + shA) + resA.y);
            *(float2*)(dB + px) = make_float2(siluf(c[mf][nf][2] * sB + shB) + resB.x,
                                              siluf(c[mf][nf][3] * sB + shB) + resB.y);
        }
    }
}

// ---------------- launch ----------------
extern "C" void kernel_launch(void* const* d_in, const int* in_sizes, int n_in,
                              void* d_out, int out_size) {
    const float* x          = (const float*)d_in[0];
    const float* w_reduce   = (const float*)d_in[1];
    const float* bn_reduce  = (const float*)d_in[2];
    const float* dcn_off_w  = (const float*)d_in[3];
    const float* dcn_off_b  = (const float*)d_in[4];
    const float* dcn_dw_w   = (const float*)d_in[5];
    const float* dcn_pw_w   = (const float*)d_in[6];
    const float* bn_dcn     = (const float*)d_in[7];
    const float* w_d2       = (const float*)d_in[8];
    const float* bn_d2      = (const float*)d_in[9];
    const float* w_d3       = (const float*)d_in[10];
    const float* bn_d3      = (const float*)d_in[11];
    const float* w_asym1    = (const float*)d_in[12];
    const float* bn_asym1   = (const float*)d_in[13];
    const float* w_asym2    = (const float*)d_in[14];
    const float* bn_asym2   = (const float*)d_in[15];
    const float* ctx_weight = (const float*)d_in[16];
    const float* bn_star    = (const float*)d_in[17];
    const float* eca_w      = (const float*)d_in[18];
    const float* sp_w       = (const float*)d_in[19];
    const float* blend_w    = (const float*)d_in[20];
    const float* w_expand   = (const float*)d_in[21];
    const float* bn_expand  = (const float*)d_in[22];
    float* out = (float*)d_out;

    static bool attr_done = false;
    if (!attr_done) {
        cudaFuncSetAttribute(k_reduce_mma, cudaFuncAttributeMaxDynamicSharedMemorySize, GEMM_SMEM);
        cudaFuncSetAttribute(k_expand_mma, cudaFuncAttributeMaxDynamicSharedMemorySize, GEMM_SMEM);
        cudaFuncSetAttribute(k_pw_mma, cudaFuncAttributeMaxDynamicSharedMemorySize, PW_SMEM);
        attr_done = true;
    }

    k_prepw<<<136, 256>>>(w_reduce, w_expand, dcn_pw_w);
    k_reduce_mma<<<dim3(HW / 128, BB), 256, GEMM_SMEM>>>(x, bn_reduce);
    k_offconv_t<<<dim3(NGRP, 5, BB), 256>>>(dcn_off_w);
    k_omsum<<<dim3(HW / 64, BB), 256>>>(dcn_off_b);
    k_sample_t<<<dim3(HW / 256, BB, 4), 256>>>();
    k_dw3x3_t<<<dim3(5, BB * CS), 256>>>(dcn_dw_w);
    k_pw_mma<<<dim3(HW / 128, BB), 256, PW_SMEM>>>(bn_dcn);
    k_ctx_star<<<dim3(5, BB * CS), 256>>>(w_d2, bn_d2, w_d3, bn_d3,
                                          w_asym1, bn_asym1, w_asym2, bn_asym2,
                                          ctx_weight, bn_star);
    k_spstat<<<dim3(HW / 64, BB), 256>>>(eca_w);
    k_satt_t<<<dim3(5, BB), 256>>>(sp_w);
    k_expand_mma<<<dim3(HW / 128, BB, 2), 256, GEMM_SMEM>>>(x, bn_expand, blend_w, out);
}